// round 4
// baseline (speedup 1.0000x reference)
#include <cuda_runtime.h>
#include <cstdint>

// ============================================================================
// Problem constants
// ============================================================================
#define NTOK 1024
#define HDIM 2048
#define NEXP 8
#define IEXP 1408
#define ISHA 5632

// ============================================================================
// Scratch (allocation-free rule: __device__ globals)
// ============================================================================
__device__ float g_act[(size_t)NTOK * ISHA];   // 23 MB, reused per expert
__device__ float g_cw[NTOK * NEXP];
__device__ float g_sg[NTOK];

// ============================================================================
// Helpers
// ============================================================================
__device__ __forceinline__ uint32_t smem_u32(const void* p) {
    uint32_t a;
    asm("{ .reg .u64 t; cvta.to.shared.u64 t, %1; cvt.u32.u64 %0, t; }" : "=r"(a) : "l"(p));
    return a;
}

__device__ __forceinline__ uint32_t f2tf32(float f) {
    uint32_t r;
    asm("cvt.rna.tf32.f32 %0, %1;" : "=r"(r) : "f"(f));
    return r;
}

__device__ __forceinline__ void cp16(uint32_t dst, const float* src) {
    asm volatile("cp.async.cg.shared.global [%0], [%1], 16;" :: "r"(dst), "l"(src));
}
#define CP_COMMIT() asm volatile("cp.async.commit_group;" ::: "memory")
#define CP_WAIT(n)  asm volatile("cp.async.wait_group %0;" :: "n"(n) : "memory")

// m16n8k8 tf32 mma: D += A*B, A row-major (4 regs), B col-major (2 regs)
__device__ __forceinline__ void mma8(float* d, const uint32_t* a, const uint32_t* b) {
    asm volatile(
        "mma.sync.aligned.m16n8k8.row.col.f32.tf32.tf32.f32 "
        "{%0,%1,%2,%3}, {%4,%5,%6,%7}, {%8,%9}, {%0,%1,%2,%3};"
        : "+f"(d[0]), "+f"(d[1]), "+f"(d[2]), "+f"(d[3])
        : "r"(a[0]), "r"(a[1]), "r"(a[2]), "r"(a[3]), "r"(b[0]), "r"(b[1]));
}

// ============================================================================
// Router: softmax + top-2 combine weights, shared-expert sigmoid gate
// ============================================================================
__global__ void router_kernel(const float* __restrict__ x,
                              const float* __restrict__ gw,
                              const float* __restrict__ sgw) {
    const int n = blockIdx.x;
    const int tid = threadIdx.x;  // 128
    const float* xr = x + (size_t)n * HDIM;
    float acc[9];
#pragma unroll
    for (int j = 0; j < 9; j++) acc[j] = 0.f;
    for (int k = tid; k < HDIM; k += 128) {
        float xv = xr[k];
#pragma unroll
        for (int e = 0; e < NEXP; e++) acc[e] += xv * gw[k * NEXP + e];
        acc[8] += xv * sgw[k];
    }
    __shared__ float red[9][4];
#pragma unroll
    for (int j = 0; j < 9; j++) {
        float v = acc[j];
#pragma unroll
        for (int o = 16; o > 0; o >>= 1) v += __shfl_xor_sync(0xffffffffu, v, o);
        if ((tid & 31) == 0) red[j][tid >> 5] = v;
    }
    __syncthreads();
    if (tid == 0) {
        float lg[9];
#pragma unroll
        for (int j = 0; j < 9; j++) lg[j] = red[j][0] + red[j][1] + red[j][2] + red[j][3];
        float m = lg[0];
        for (int e = 1; e < NEXP; e++) m = fmaxf(m, lg[e]);
        float p[NEXP], s = 0.f;
        for (int e = 0; e < NEXP; e++) { p[e] = expf(lg[e] - m); s += p[e]; }
        for (int e = 0; e < NEXP; e++) p[e] /= s;
        int i1 = 0;
        for (int e = 1; e < NEXP; e++) if (p[e] > p[i1]) i1 = e;
        int i2 = (i1 == 0) ? 1 : 0;
        for (int e = 0; e < NEXP; e++) if (e != i1 && p[e] > p[i2]) i2 = e;
        for (int e = 0; e < NEXP; e++)
            g_cw[n * NEXP + e] = (e == i1 || e == i2) ? p[e] : 0.f;
        g_sg[n] = 1.f / (1.f + expf(-lg[8]));
    }
}

// ============================================================================
// Fused gate_up GEMM + SiLU*mul  (mma.sync tf32, cp.async double buffer)
//   X [NTOK, HDIM], W [HDIM, 2F] (gate cols [0,F), up cols [F,2F))
//   CTA tile: 128 rows x 64 feature cols (each half). 256 threads, 8 warps.
//   SMEM: As[2][128][36], Bg[2][32][72], Bu[2][32][72]  (floats)
// ============================================================================
#define GU_ASZ (128 * 36)
#define GU_BSZ (32 * 72)
#define GU_BUF (GU_ASZ + 2 * GU_BSZ)            // floats per buffer = 9216
#define GU_SMEM (2 * GU_BUF * 4)                // 73728 bytes

__device__ __forceinline__ void gu_load(uint32_t sb, int buf,
                                        const float* __restrict__ X,
                                        const float* __restrict__ W,
                                        int F, int ldw, int m0, int f0,
                                        int kt, int tid) {
    const int k0 = kt * 32;
    uint32_t abase = sb + (buf * GU_BUF) * 4;
    uint32_t gbase = abase + GU_ASZ * 4;
#pragma unroll
    for (int i = 0; i < 4; i++) {           // A: 1024 float4
        int idx = tid + i * 256;
        int row = idx >> 3, q = idx & 7;
        cp16(abase + (row * 36 + q * 4) * 4, X + (size_t)(m0 + row) * HDIM + k0 + q * 4);
    }
#pragma unroll
    for (int i = 0; i < 4; i++) {           // B: 2 halves x 512 float4
        int idx = tid + i * 256;
        int half = idx >> 9;
        int r = (idx >> 4) & 31, q = idx & 15;
        uint32_t dst = gbase + (half * GU_BSZ + r * 72 + q * 4) * 4;
        const float* src = W + (size_t)(k0 + r) * ldw + (half ? F + f0 : f0) + q * 4;
        cp16(dst, src);
    }
}

__global__ __launch_bounds__(256) void gateup_kernel(const float* __restrict__ X,
                                                     const float* __restrict__ W,
                                                     int F) {
    extern __shared__ float smem[];
    const int tid = threadIdx.x;
    const int wid = tid >> 5, lane = tid & 31;
    const int gid = lane >> 2, tg = lane & 3;
    const int warp_m = (wid & 3) * 32;
    const int warp_n = (wid >> 2) * 32;
    const int f0 = blockIdx.x * 64;
    const int m0 = blockIdx.y * 128;
    const int ldw = 2 * F;
    const int kIters = HDIM / 32;  // 64
    const uint32_t sb = smem_u32(smem);

    float cg[2][4][4], cu[2][4][4];
#pragma unroll
    for (int mf = 0; mf < 2; mf++)
#pragma unroll
        for (int nf = 0; nf < 4; nf++)
#pragma unroll
            for (int r = 0; r < 4; r++) { cg[mf][nf][r] = 0.f; cu[mf][nf][r] = 0.f; }

    gu_load(sb, 0, X, W, F, ldw, m0, f0, 0, tid);
    CP_COMMIT();

    int buf = 0;
    for (int kt = 0; kt < kIters; kt++) {
        if (kt + 1 < kIters) {
            gu_load(sb, buf ^ 1, X, W, F, ldw, m0, f0, kt + 1, tid);
            CP_COMMIT();
            CP_WAIT(1);
        } else {
            CP_WAIT(0);
        }
        __syncthreads();

        const float* As = smem + buf * GU_BUF;
        const float* Bg = As + GU_ASZ;
        const float* Bu = Bg + GU_BSZ;
#pragma unroll
        for (int ks = 0; ks < 4; ks++) {
            const int k0 = ks * 8;
            uint32_t a[2][4];
#pragma unroll
            for (int mf = 0; mf < 2; mf++) {
                int r = warp_m + mf * 16 + gid;
                a[mf][0] = f2tf32(As[r * 36 + k0 + tg]);
                a[mf][1] = f2tf32(As[(r + 8) * 36 + k0 + tg]);
                a[mf][2] = f2tf32(As[r * 36 + k0 + tg + 4]);
                a[mf][3] = f2tf32(As[(r + 8) * 36 + k0 + tg + 4]);
            }
#pragma unroll
            for (int nf = 0; nf < 4; nf++) {
                int n = warp_n + nf * 8 + gid;
                uint32_t bg[2], bu[2];
                bg[0] = f2tf32(Bg[(k0 + tg) * 72 + n]);
                bg[1] = f2tf32(Bg[(k0 + tg + 4) * 72 + n]);
                bu[0] = f2tf32(Bu[(k0 + tg) * 72 + n]);
                bu[1] = f2tf32(Bu[(k0 + tg + 4) * 72 + n]);
#pragma unroll
                for (int mf = 0; mf < 2; mf++) {
                    mma8(cg[mf][nf], a[mf], bg);
                    mma8(cu[mf][nf], a[mf], bu);
                }
            }
        }
        __syncthreads();
        buf ^= 1;
    }

    // Epilogue: silu(gate) * up -> g_act
#pragma unroll
    for (int mf = 0; mf < 2; mf++) {
        int r0 = m0 + warp_m + mf * 16 + gid;
#pragma unroll
        for (int nf = 0; nf < 4; nf++) {
            int c0 = f0 + warp_n + nf * 8 + 2 * tg;
#pragma unroll
            for (int e = 0; e < 4; e++) {
                int row = r0 + (e >> 1) * 8;
                int col = c0 + (e & 1);
                float gv = cg[mf][nf][e];
                float uv = cu[mf][nf][e];
                float sv = gv / (1.0f + __expf(-gv));
                g_act[(size_t)row * F + col] = sv * uv;
            }
        }
    }
}

// ============================================================================
// Down GEMM + scaled combine  (mma.sync tf32, cp.async double buffer)
//   act [NTOK, Fk] (g_act), Wd [Fk, HDIM], CTA 128x128xk32, 256 threads
//   mode 0: out = g_sg[m] * acc     (initializes out)
//   mode 1+e: out += g_cw[m,e] * acc (skip rows with weight 0)
//   SMEM: As[2][128][36], Bs[2][32][136]
// ============================================================================
#define DN_ASZ (128 * 36)
#define DN_BSZ (32 * 136)
#define DN_BUF (DN_ASZ + DN_BSZ)                // 8960 floats
#define DN_SMEM (2 * DN_BUF * 4)                // 71680 bytes

__device__ __forceinline__ void dn_load(uint32_t sb, int buf,
                                        const float* __restrict__ A,
                                        const float* __restrict__ Wd,
                                        int Fk, int m0, int n0, int kt, int tid) {
    const int k0 = kt * 32;
    uint32_t abase = sb + (buf * DN_BUF) * 4;
    uint32_t bbase = abase + DN_ASZ * 4;
#pragma unroll
    for (int i = 0; i < 4; i++) {
        int idx = tid + i * 256;
        int row = idx >> 3, q = idx & 7;
        cp16(abase + (row * 36 + q * 4) * 4, A + (size_t)(m0 + row) * Fk + k0 + q * 4);
    }
#pragma unroll
    for (int i = 0; i < 4; i++) {
        int idx = tid + i * 256;
        int r = idx >> 5, q = idx & 31;     // 32 k-rows x 32 float4
        cp16(bbase + (r * 136 + q * 4) * 4, Wd + (size_t)(k0 + r) * HDIM + n0 + q * 4);
    }
}

__global__ __launch_bounds__(256) void down_kernel(const float* __restrict__ Wd,
                                                   float* __restrict__ out,
                                                   int Fk, int mode) {
    extern __shared__ float smem[];
    const int tid = threadIdx.x;
    const int wid = tid >> 5, lane = tid & 31;
    const int gid = lane >> 2, tg = lane & 3;
    const int warp_m = (wid & 3) * 32;
    const int warp_n = (wid >> 2) * 64;
    const int n0 = blockIdx.x * 128;
    const int m0 = blockIdx.y * 128;
    const int kIters = Fk / 32;
    const uint32_t sb = smem_u32(smem);

    float acc[2][8][4];
#pragma unroll
    for (int mf = 0; mf < 2; mf++)
#pragma unroll
        for (int nf = 0; nf < 8; nf++)
#pragma unroll
            for (int r = 0; r < 4; r++) acc[mf][nf][r] = 0.f;

    dn_load(sb, 0, g_act, Wd, Fk, m0, n0, 0, tid);
    CP_COMMIT();

    int buf = 0;
    for (int kt = 0; kt < kIters; kt++) {
        if (kt + 1 < kIters) {
            dn_load(sb, buf ^ 1, g_act, Wd, Fk, m0, n0, kt + 1, tid);
            CP_COMMIT();
            CP_WAIT(1);
        } else {
            CP_WAIT(0);
        }
        __syncthreads();

        const float* As = smem + buf * DN_BUF;
        const float* Bs = As + DN_ASZ;
#pragma unroll
        for (int ks = 0; ks < 4; ks++) {
            const int k0 = ks * 8;
            uint32_t a[2][4];
#pragma unroll
            for (int mf = 0; mf < 2; mf++) {
                int r = warp_m + mf * 16 + gid;
                a[mf][0] = f2tf32(As[r * 36 + k0 + tg]);
                a[mf][1] = f2tf32(As[(r + 8) * 36 + k0 + tg]);
                a[mf][2] = f2tf32(As[r * 36 + k0 + tg + 4]);
                a[mf][3] = f2tf32(As[(r + 8) * 36 + k0 + tg + 4]);
            }
#pragma unroll
            for (int nf = 0; nf < 8; nf++) {
                int n = warp_n + nf * 8 + gid;
                uint32_t b[2];
                b[0] = f2tf32(Bs[(k0 + tg) * 136 + n]);
                b[1] = f2tf32(Bs[(k0 + tg + 4) * 136 + n]);
#pragma unroll
                for (int mf = 0; mf < 2; mf++) mma8(acc[mf][nf], a[mf], b);
            }
        }
        __syncthreads();
        buf ^= 1;
    }

    // Epilogue: scale + combine. 4 distinct rows per thread.
    float w[2][2];
#pragma unroll
    for (int mf = 0; mf < 2; mf++)
#pragma unroll
        for (int h = 0; h < 2; h++) {
            int row = m0 + warp_m + mf * 16 + gid + h * 8;
            w[mf][h] = (mode == 0) ? g_sg[row] : g_cw[row * NEXP + (mode - 1)];
        }

#pragma unroll
    for (int mf = 0; mf < 2; mf++) {
        int r0 = m0 + warp_m + mf * 16 + gid;
#pragma unroll
        for (int h = 0; h < 2; h++) {
            int row = r0 + h * 8;
            float wv = w[mf][h];
            if (mode != 0 && wv == 0.f) continue;
#pragma unroll
            for (int nf = 0; nf < 8; nf++) {
                int col = n0 + warp_n + nf * 8 + 2 * tg;
                float v0 = wv * acc[mf][nf][2 * h];
                float v1 = wv * acc[mf][nf][2 * h + 1];
                float* o = out + (size_t)row * HDIM + col;
                if (mode == 0) { o[0] = v0; o[1] = v1; }
                else           { o[0] += v0; o[1] += v1; }
            }
        }
    }
}

// ============================================================================
// Launch
// ============================================================================
extern "C" void kernel_launch(void* const* d_in, const int* in_sizes, int n_in,
                              void* d_out, int out_size) {
    const float* x = (const float*)d_in[0];       // [1024, 2048]
    const float* gw = (const float*)d_in[1];      // [2048, 8]
    const float* wgu = (const float*)d_in[2];     // [8, 2048, 2816]
    const float* wdn = (const float*)d_in[3];     // [8, 1408, 2048]
    const float* swgu = (const float*)d_in[4];    // [2048, 11264]
    const float* swdn = (const float*)d_in[5];    // [5632, 2048]
    const float* sgw = (const float*)d_in[6];     // [2048, 1]
    float* out = (float*)d_out;                   // [1024, 2048]

    cudaFuncSetAttribute(gateup_kernel, cudaFuncAttributeMaxDynamicSharedMemorySize, GU_SMEM);
    cudaFuncSetAttribute(down_kernel, cudaFuncAttributeMaxDynamicSharedMemorySize, DN_SMEM);

    router_kernel<<<NTOK, 128>>>(x, gw, sgw);

    // Shared expert first: its down-GEMM initializes (overwrites) the whole out.
    gateup_kernel<<<dim3(ISHA / 64, NTOK / 128), 256, GU_SMEM>>>(x, swgu, ISHA);
    down_kernel<<<dim3(HDIM / 128, NTOK / 128), 256, DN_SMEM>>>(swdn, out, ISHA, 0);

    // Routed experts (dense compute, zero-weight epilogue row skip).
    for (int e = 0; e < NEXP; e++) {
        gateup_kernel<<<dim3(IEXP / 64, NTOK / 128), 256, GU_SMEM>>>(
            x, wgu + (size_t)e * HDIM * 2 * IEXP, IEXP);
        down_kernel<<<dim3(HDIM / 128, NTOK / 128), 256, DN_SMEM>>>(
            wdn + (size_t)e * IEXP * HDIM, out, IEXP, 1 + e);
    }
}

// round 6
// speedup vs baseline: 1.1847x; 1.1847x over previous
#include <cuda_runtime.h>
#include <cstdint>

// ============================================================================
// Problem constants
// ============================================================================
#define NTOK 1024
#define HDIM 2048
#define NEXP 8
#define IEXP 1408
#define ISHA 5632

// ============================================================================
// Scratch (allocation-free rule: __device__ globals)
// ============================================================================
__device__ float g_act[(size_t)NTOK * ISHA];   // 23 MB, reused per expert (slot-indexed)
__device__ float g_sg[NTOK];
__device__ int   g_cnt[NEXP];
__device__ int   g_tok[NEXP * NTOK];           // expert -> token list
__device__ float g_wt[NEXP * NTOK];            // expert -> routing weight per slot

// ============================================================================
// Helpers
// ============================================================================
__device__ __forceinline__ uint32_t smem_u32(const void* p) {
    uint32_t a;
    asm("{ .reg .u64 t; cvta.to.shared.u64 t, %1; cvt.u32.u64 %0, t; }" : "=r"(a) : "l"(p));
    return a;
}

__device__ __forceinline__ uint32_t f2tf32(float f) {
    uint32_t r;
    asm("cvt.rna.tf32.f32 %0, %1;" : "=r"(r) : "f"(f));
    return r;
}

__device__ __forceinline__ void cp16(uint32_t dst, const float* src) {
    asm volatile("cp.async.cg.shared.global [%0], [%1], 16;" :: "r"(dst), "l"(src));
}
#define CP_COMMIT() asm volatile("cp.async.commit_group;" ::: "memory")
#define CP_WAIT(n)  asm volatile("cp.async.wait_group %0;" :: "n"(n) : "memory")

// m16n8k8 tf32 mma: D += A*B, A row-major (4 regs), B col-major (2 regs)
__device__ __forceinline__ void mma8(float* d, const uint32_t* a, const uint32_t* b) {
    asm volatile(
        "mma.sync.aligned.m16n8k8.row.col.f32.tf32.tf32.f32 "
        "{%0,%1,%2,%3}, {%4,%5,%6,%7}, {%8,%9}, {%0,%1,%2,%3};"
        : "+f"(d[0]), "+f"(d[1]), "+f"(d[2]), "+f"(d[3])
        : "r"(a[0]), "r"(a[1]), "r"(a[2]), "r"(a[3]), "r"(b[0]), "r"(b[1]));
}

// ============================================================================
// Zero per-launch state (counts rebuilt every call: graph replays)
// ============================================================================
__global__ void zero_kernel() {
    if (threadIdx.x < NEXP) g_cnt[threadIdx.x] = 0;
}

// ============================================================================
// Router: softmax + top-2 -> per-expert token lists; shared sigmoid gate
// ============================================================================
__global__ void router_kernel(const float* __restrict__ x,
                              const float* __restrict__ gw,
                              const float* __restrict__ sgw) {
    const int n = blockIdx.x;
    const int tid = threadIdx.x;  // 128
    const float* xr = x + (size_t)n * HDIM;
    float acc[9];
#pragma unroll
    for (int j = 0; j < 9; j++) acc[j] = 0.f;
    for (int k = tid; k < HDIM; k += 128) {
        float xv = xr[k];
#pragma unroll
        for (int e = 0; e < NEXP; e++) acc[e] += xv * gw[k * NEXP + e];
        acc[8] += xv * sgw[k];
    }
    __shared__ float red[9][4];
#pragma unroll
    for (int j = 0; j < 9; j++) {
        float v = acc[j];
#pragma unroll
        for (int o = 16; o > 0; o >>= 1) v += __shfl_xor_sync(0xffffffffu, v, o);
        if ((tid & 31) == 0) red[j][tid >> 5] = v;
    }
    __syncthreads();
    if (tid == 0) {
        float lg[9];
#pragma unroll
        for (int j = 0; j < 9; j++) lg[j] = red[j][0] + red[j][1] + red[j][2] + red[j][3];
        float m = lg[0];
        for (int e = 1; e < NEXP; e++) m = fmaxf(m, lg[e]);
        float p[NEXP], s = 0.f;
        for (int e = 0; e < NEXP; e++) { p[e] = expf(lg[e] - m); s += p[e]; }
        for (int e = 0; e < NEXP; e++) p[e] /= s;
        int i1 = 0;
        for (int e = 1; e < NEXP; e++) if (p[e] > p[i1]) i1 = e;
        int i2 = (i1 == 0) ? 1 : 0;
        for (int e = 0; e < NEXP; e++) if (e != i1 && p[e] > p[i2]) i2 = e;
        int s1 = atomicAdd(&g_cnt[i1], 1);
        g_tok[i1 * NTOK + s1] = n;  g_wt[i1 * NTOK + s1] = p[i1];
        int s2 = atomicAdd(&g_cnt[i2], 1);
        g_tok[i2 * NTOK + s2] = n;  g_wt[i2 * NTOK + s2] = p[i2];
        g_sg[n] = 1.f / (1.f + expf(-lg[8]));
    }
}

// ============================================================================
// Fused gate_up GEMM + SiLU*mul  (mma.sync tf32, 3-stage cp.async pipeline)
//   expert >= 0: rows gathered via g_tok[expert]; writes g_act by slot
//   expert <  0: dense (shared expert), rows = tokens
//   CTA: 128 rows x 64 feature cols per half (gate+up). 256 threads, 8 warps.
//   SMEM stage: As[128][36], Bg[32][72], Bu[32][72]
// ============================================================================
#define GU_ASZ (128 * 36)
#define GU_BSZ (32 * 72)
#define GU_BUF (GU_ASZ + 2 * GU_BSZ)            // 9216 floats / stage
#define GU_SMEM (3 * GU_BUF * 4)                // 110592 bytes

__global__ __launch_bounds__(256) void gateup_kernel(const float* __restrict__ X,
                                                     const float* __restrict__ W,
                                                     int F, int expert) {
    const int tid = threadIdx.x;
    const int f0 = blockIdx.x * 64;
    const int m0 = blockIdx.y * 128;
    int cnt = NTOK;
    if (expert >= 0) {
        cnt = g_cnt[expert];
        if (m0 >= cnt) return;
    }
    extern __shared__ float smem[];
    const int wid = tid >> 5, lane = tid & 31;
    const int gid = lane >> 2, tg = lane & 3;
    const int warp_m = (wid & 3) * 32;
    const int warp_n = (wid >> 2) * 32;
    const int ldw = 2 * F;
    const int kIters = HDIM / 32;  // 64
    const uint32_t sb = smem_u32(smem);

    // Precompute per-thread staging sources/dests (fixed across k-iters)
    const float* aSrc[4];
    uint32_t aOff[4];
#pragma unroll
    for (int i = 0; i < 4; i++) {
        int idx = tid + i * 256;
        int row = idx >> 3, q = idx & 7;
        int t;
        if (expert >= 0)
            t = g_tok[expert * NTOK + ((m0 + row < cnt) ? (m0 + row) : 0)];
        else
            t = m0 + row;
        aSrc[i] = X + (size_t)t * HDIM + q * 4;
        aOff[i] = (uint32_t)(row * 36 + q * 4) * 4;
    }
    const float* bSrc[4];
    uint32_t bOff[4];
#pragma unroll
    for (int i = 0; i < 4; i++) {
        int idx = tid + i * 256;
        int half = idx >> 9;
        int r = (idx >> 4) & 31, q = idx & 15;
        bSrc[i] = W + (size_t)r * ldw + (half ? F + f0 : f0) + q * 4;
        bOff[i] = (uint32_t)(GU_ASZ + half * GU_BSZ + r * 72 + q * 4) * 4;
    }

    float cg[2][4][4], cu[2][4][4];
#pragma unroll
    for (int mf = 0; mf < 2; mf++)
#pragma unroll
        for (int nf = 0; nf < 4; nf++)
#pragma unroll
            for (int r = 0; r < 4; r++) { cg[mf][nf][r] = 0.f; cu[mf][nf][r] = 0.f; }

    // Prologue: stages 0 and 1
#pragma unroll
    for (int s = 0; s < 2; s++) {
        uint32_t base = sb + (s * GU_BUF) * 4;
        const int k0 = s * 32;
#pragma unroll
        for (int i = 0; i < 4; i++) cp16(base + aOff[i], aSrc[i] + k0);
#pragma unroll
        for (int i = 0; i < 4; i++) cp16(base + bOff[i], bSrc[i] + (size_t)k0 * ldw);
        CP_COMMIT();
    }

    int buf = 0;
    for (int kt = 0; kt < kIters; kt++) {
        CP_WAIT(1);
        __syncthreads();
        if (kt + 2 < kIters) {
            int nb = buf + 2; if (nb >= 3) nb -= 3;
            uint32_t base = sb + (nb * GU_BUF) * 4;
            const int k0 = (kt + 2) * 32;
#pragma unroll
            for (int i = 0; i < 4; i++) cp16(base + aOff[i], aSrc[i] + k0);
#pragma unroll
            for (int i = 0; i < 4; i++) cp16(base + bOff[i], bSrc[i] + (size_t)k0 * ldw);
        }
        CP_COMMIT();  // empty group in tail keeps wait_group accounting valid

        const float* As = smem + buf * GU_BUF;
        const float* Bg = As + GU_ASZ;
        const float* Bu = Bg + GU_BSZ;
#pragma unroll
        for (int ks = 0; ks < 4; ks++) {
            const int k0 = ks * 8;
            uint32_t a[2][4];
#pragma unroll
            for (int mf = 0; mf < 2; mf++) {
                int r = warp_m + mf * 16 + gid;
                a[mf][0] = f2tf32(As[r * 36 + k0 + tg]);
                a[mf][1] = f2tf32(As[(r + 8) * 36 + k0 + tg]);
                a[mf][2] = f2tf32(As[r * 36 + k0 + tg + 4]);
                a[mf][3] = f2tf32(As[(r + 8) * 36 + k0 + tg + 4]);
            }
#pragma unroll
            for (int nf = 0; nf < 4; nf++) {
                int n = warp_n + nf * 8 + gid;
                uint32_t bg[2], bu[2];
                bg[0] = f2tf32(Bg[(k0 + tg) * 72 + n]);
                bg[1] = f2tf32(Bg[(k0 + tg + 4) * 72 + n]);
                bu[0] = f2tf32(Bu[(k0 + tg) * 72 + n]);
                bu[1] = f2tf32(Bu[(k0 + tg + 4) * 72 + n]);
#pragma unroll
                for (int mf = 0; mf < 2; mf++) {
                    mma8(cg[mf][nf], a[mf], bg);
                    mma8(cu[mf][nf], a[mf], bu);
                }
            }
        }
        buf++; if (buf >= 3) buf -= 3;
    }

    // Epilogue: silu(gate) * up -> g_act (slot-indexed rows)
#pragma unroll
    for (int mf = 0; mf < 2; mf++) {
        int r0 = m0 + warp_m + mf * 16 + gid;
#pragma unroll
        for (int nf = 0; nf < 4; nf++) {
            int c0 = f0 + warp_n + nf * 8 + 2 * tg;
#pragma unroll
            for (int e = 0; e < 4; e++) {
                int row = r0 + (e >> 1) * 8;
                int col = c0 + (e & 1);
                float gv = cg[mf][nf][e];
                float uv = cu[mf][nf][e];
                float sv = gv / (1.0f + __expf(-gv));
                g_act[(size_t)row * F + col] = sv * uv;
            }
        }
    }
}

// ============================================================================
// Down GEMM + scaled combine  (mma.sync tf32, 3-stage pipeline)
//   act (g_act, slot rows) @ Wd [Fk, HDIM]; CTA 128x128, 256 threads
//   expert <  0: out[token] = g_sg[token] * acc    (dense init, token = slot)
//   expert >= 0: out[g_tok[slot]] += g_wt[slot] * acc  (guard slot < cnt)
//   SMEM stage: As[128][36], Bs[32][136]
// ============================================================================
#define DN_ASZ (128 * 36)
#define DN_BSZ (32 * 136)
#define DN_BUF (DN_ASZ + DN_BSZ)                // 8960 floats / stage
#define DN_SMEM (3 * DN_BUF * 4)                // 107520 bytes

__global__ __launch_bounds__(256) void down_kernel(const float* __restrict__ Wd,
                                                   float* __restrict__ out,
                                                   int Fk, int expert) {
    const int tid = threadIdx.x;
    const int n0 = blockIdx.x * 128;
    const int m0 = blockIdx.y * 128;
    int cnt = NTOK;
    if (expert >= 0) {
        cnt = g_cnt[expert];
        if (m0 >= cnt) return;
    }
    extern __shared__ float smem[];
    const int wid = tid >> 5, lane = tid & 31;
    const int gid = lane >> 2, tg = lane & 3;
    const int warp_m = (wid & 3) * 32;
    const int warp_n = (wid >> 2) * 64;
    const int kIters = Fk / 32;
    const uint32_t sb = smem_u32(smem);

    const float* aSrc[4];
    uint32_t aOff[4];
#pragma unroll
    for (int i = 0; i < 4; i++) {
        int idx = tid + i * 256;
        int row = idx >> 3, q = idx & 7;
        aSrc[i] = g_act + (size_t)(m0 + row) * Fk + q * 4;
        aOff[i] = (uint32_t)(row * 36 + q * 4) * 4;
    }
    const float* bSrc[4];
    uint32_t bOff[4];
#pragma unroll
    for (int i = 0; i < 4; i++) {
        int idx = tid + i * 256;
        int r = idx >> 5, q = idx & 31;
        bSrc[i] = Wd + (size_t)r * HDIM + n0 + q * 4;
        bOff[i] = (uint32_t)(DN_ASZ + r * 136 + q * 4) * 4;
    }

    float acc[2][8][4];
#pragma unroll
    for (int mf = 0; mf < 2; mf++)
#pragma unroll
        for (int nf = 0; nf < 8; nf++)
#pragma unroll
            for (int r = 0; r < 4; r++) acc[mf][nf][r] = 0.f;

#pragma unroll
    for (int s = 0; s < 2; s++) {
        uint32_t base = sb + (s * DN_BUF) * 4;
        const int k0 = s * 32;
#pragma unroll
        for (int i = 0; i < 4; i++) cp16(base + aOff[i], aSrc[i] + k0);
#pragma unroll
        for (int i = 0; i < 4; i++) cp16(base + bOff[i], bSrc[i] + (size_t)k0 * HDIM);
        CP_COMMIT();
    }

    int buf = 0;
    for (int kt = 0; kt < kIters; kt++) {
        CP_WAIT(1);
        __syncthreads();
        if (kt + 2 < kIters) {
            int nb = buf + 2; if (nb >= 3) nb -= 3;
            uint32_t base = sb + (nb * DN_BUF) * 4;
            const int k0 = (kt + 2) * 32;
#pragma unroll
            for (int i = 0; i < 4; i++) cp16(base + aOff[i], aSrc[i] + k0);
#pragma unroll
            for (int i = 0; i < 4; i++) cp16(base + bOff[i], bSrc[i] + (size_t)k0 * HDIM);
        }
        CP_COMMIT();

        const float* As = smem + buf * DN_BUF;
        const float* Bs = As + DN_ASZ;
#pragma unroll
        for (int ks = 0; ks < 4; ks++) {
            const int k0 = ks * 8;
            uint32_t a[2][4];
#pragma unroll
            for (int mf = 0; mf < 2; mf++) {
                int r = warp_m + mf * 16 + gid;
                a[mf][0] = f2tf32(As[r * 36 + k0 + tg]);
                a[mf][1] = f2tf32(As[(r + 8) * 36 + k0 + tg]);
                a[mf][2] = f2tf32(As[r * 36 + k0 + tg + 4]);
                a[mf][3] = f2tf32(As[(r + 8) * 36 + k0 + tg + 4]);
            }
#pragma unroll
            for (int nf = 0; nf < 8; nf++) {
                int n = warp_n + nf * 8 + gid;
                uint32_t b[2];
                b[0] = f2tf32(Bs[(k0 + tg) * 136 + n]);
                b[1] = f2tf32(Bs[(k0 + tg + 4) * 136 + n]);
#pragma unroll
                for (int mf = 0; mf < 2; mf++) mma8(acc[mf][nf], a[mf], b);
            }
        }
        buf++; if (buf >= 3) buf -= 3;
    }

    // Epilogue: scale + combine (scatter for routed experts)
#pragma unroll
    for (int mf = 0; mf < 2; mf++) {
        int r0 = m0 + warp_m + mf * 16 + gid;
#pragma unroll
        for (int h = 0; h < 2; h++) {
            int slot = r0 + h * 8;
            int token; float wv;
            if (expert >= 0) {
                if (slot >= cnt) continue;
                token = g_tok[expert * NTOK + slot];
                wv = g_wt[expert * NTOK + slot];
            } else {
                token = slot;
                wv = g_sg[slot];
            }
#pragma unroll
            for (int nf = 0; nf < 8; nf++) {
                int col = n0 + warp_n + nf * 8 + 2 * tg;
                float v0 = wv * acc[mf][nf][2 * h];
                float v1 = wv * acc[mf][nf][2 * h + 1];
                float* o = out + (size_t)token * HDIM + col;
                if (expert >= 0) { o[0] += v0; o[1] += v1; }
                else             { o[0] = v0;  o[1] = v1;  }
            }
        }
    }
}

// ============================================================================
// Launch
// ============================================================================
extern "C" void kernel_launch(void* const* d_in, const int* in_sizes, int n_in,
                              void* d_out, int out_size) {
    const float* x = (const float*)d_in[0];       // [1024, 2048]
    const float* gw = (const float*)d_in[1];      // [2048, 8]
    const float* wgu = (const float*)d_in[2];     // [8, 2048, 2816]
    const float* wdn = (const float*)d_in[3];     // [8, 1408, 2048]
    const float* swgu = (const float*)d_in[4];    // [2048, 11264]
    const float* swdn = (const float*)d_in[5];    // [5632, 2048]
    const float* sgw = (const float*)d_in[6];     // [2048, 1]
    float* out = (float*)d_out;                   // [1024, 2048]

    cudaFuncSetAttribute(gateup_kernel, cudaFuncAttributeMaxDynamicSharedMemorySize, GU_SMEM);
    cudaFuncSetAttribute(down_kernel, cudaFuncAttributeMaxDynamicSharedMemorySize, DN_SMEM);

    zero_kernel<<<1, 32>>>();
    router_kernel<<<NTOK, 128>>>(x, gw, sgw);

    // Shared expert first: its down-GEMM initializes (overwrites) the whole out.
    gateup_kernel<<<dim3(ISHA / 64, NTOK / 128), 256, GU_SMEM>>>(x, swgu, ISHA, -1);
    down_kernel<<<dim3(HDIM / 128, NTOK / 128), 256, DN_SMEM>>>(swdn, out, ISHA, -1);

    // Routed experts: gathered rows, early-exit tiles past each expert's count.
    for (int e = 0; e < NEXP; e++) {
        gateup_kernel<<<dim3(IEXP / 64, NTOK / 128), 256, GU_SMEM>>>(
            x, wgu + (size_t)e * HDIM * 2 * IEXP, IEXP, e);
        down_kernel<<<dim3(HDIM / 128, NTOK / 128), 256, DN_SMEM>>>(
            wdn + (size_t)e * IEXP * HDIM, out, IEXP, e);
    }
}

// round 7
// speedup vs baseline: 2.3461x; 1.9804x over previous
#include <cuda_runtime.h>
#include <cstdint>

// ============================================================================
// Problem constants
// ============================================================================
#define NTOK 1024
#define HDIM 2048
#define NEXP 8
#define IEXP 1408
#define ISHA 5632

// ============================================================================
// Scratch (allocation-free rule: __device__ globals)
// ============================================================================
__device__ float g_xr[(size_t)NTOK * HDIM];            // pre-rounded x (8MB)
__device__ float g_acts[(size_t)NTOK * ISHA];          // shared act (23MB, pre-rounded)
__device__ float g_actr[(size_t)NEXP * NTOK * IEXP];   // routed act (46MB, pre-rounded)
__device__ float g_eo[(size_t)NEXP * NTOK * HDIM];     // routed expert out (67MB)
__device__ float g_sg[NTOK];
__device__ int   g_cnt[NEXP];
__device__ int   g_tok[NEXP * NTOK];                   // expert -> token list
__device__ float g_wt[NEXP * NTOK];                    // expert -> routing weight / slot
__device__ int   g_slot[NTOK * 2];                     // token -> 2 global slots

// ============================================================================
// Helpers
// ============================================================================
__device__ __forceinline__ uint32_t smem_u32(const void* p) {
    uint32_t a;
    asm("{ .reg .u64 t; cvta.to.shared.u64 t, %1; cvt.u32.u64 %0, t; }" : "=r"(a) : "l"(p));
    return a;
}

__device__ __forceinline__ uint32_t f2tf32(float f) {
    uint32_t r;
    asm("cvt.rna.tf32.f32 %0, %1;" : "=r"(r) : "f"(f));
    return r;
}

__device__ __forceinline__ void cp16(uint32_t dst, const float* src) {
    asm volatile("cp.async.cg.shared.global [%0], [%1], 16;" :: "r"(dst), "l"(src));
}
#define CP_COMMIT() asm volatile("cp.async.commit_group;" ::: "memory")
#define CP_WAIT(n)  asm volatile("cp.async.wait_group %0;" :: "n"(n) : "memory")

// m16n8k8 tf32 mma: D += A*B, A row-major (4 regs), B col-major (2 regs)
__device__ __forceinline__ void mma8(float* d, const uint32_t* a, const uint32_t* b) {
    asm volatile(
        "mma.sync.aligned.m16n8k8.row.col.f32.tf32.tf32.f32 "
        "{%0,%1,%2,%3}, {%4,%5,%6,%7}, {%8,%9}, {%0,%1,%2,%3};"
        : "+f"(d[0]), "+f"(d[1]), "+f"(d[2]), "+f"(d[3])
        : "r"(a[0]), "r"(a[1]), "r"(a[2]), "r"(a[3]), "r"(b[0]), "r"(b[1]));
}

// ============================================================================
// Small kernels
// ============================================================================
__global__ void zero_kernel() {
    if (threadIdx.x < NEXP) g_cnt[threadIdx.x] = 0;
}

// Pre-round x to tf32 precision (g_xr). grid 2048 x 256thr, float4 each.
__global__ void roundx_kernel(const float* __restrict__ x) {
    int idx = blockIdx.x * 256 + threadIdx.x;
    float4 v = reinterpret_cast<const float4*>(x)[idx];
    float4 o;
    o.x = __uint_as_float(f2tf32(v.x));
    o.y = __uint_as_float(f2tf32(v.y));
    o.z = __uint_as_float(f2tf32(v.z));
    o.w = __uint_as_float(f2tf32(v.w));
    reinterpret_cast<float4*>(g_xr)[idx] = o;
}

// ============================================================================
// Router: softmax + top-2 -> per-expert token lists + token->slot map
// ============================================================================
__global__ void router_kernel(const float* __restrict__ x,
                              const float* __restrict__ gw,
                              const float* __restrict__ sgw) {
    const int n = blockIdx.x;
    const int tid = threadIdx.x;  // 128
    const float* xr = x + (size_t)n * HDIM;
    float acc[9];
#pragma unroll
    for (int j = 0; j < 9; j++) acc[j] = 0.f;
    for (int k = tid; k < HDIM; k += 128) {
        float xv = xr[k];
#pragma unroll
        for (int e = 0; e < NEXP; e++) acc[e] += xv * gw[k * NEXP + e];
        acc[8] += xv * sgw[k];
    }
    __shared__ float red[9][4];
#pragma unroll
    for (int j = 0; j < 9; j++) {
        float v = acc[j];
#pragma unroll
        for (int o = 16; o > 0; o >>= 1) v += __shfl_xor_sync(0xffffffffu, v, o);
        if ((tid & 31) == 0) red[j][tid >> 5] = v;
    }
    __syncthreads();
    if (tid == 0) {
        float lg[9];
#pragma unroll
        for (int j = 0; j < 9; j++) lg[j] = red[j][0] + red[j][1] + red[j][2] + red[j][3];
        float m = lg[0];
        for (int e = 1; e < NEXP; e++) m = fmaxf(m, lg[e]);
        float p[NEXP], s = 0.f;
        for (int e = 0; e < NEXP; e++) { p[e] = expf(lg[e] - m); s += p[e]; }
        for (int e = 0; e < NEXP; e++) p[e] /= s;
        int i1 = 0;
        for (int e = 1; e < NEXP; e++) if (p[e] > p[i1]) i1 = e;
        int i2 = (i1 == 0) ? 1 : 0;
        for (int e = 0; e < NEXP; e++) if (e != i1 && p[e] > p[i2]) i2 = e;
        int s1 = atomicAdd(&g_cnt[i1], 1);
        g_tok[i1 * NTOK + s1] = n;  g_wt[i1 * NTOK + s1] = p[i1];
        g_slot[n * 2] = i1 * NTOK + s1;
        int s2 = atomicAdd(&g_cnt[i2], 1);
        g_tok[i2 * NTOK + s2] = n;  g_wt[i2 * NTOK + s2] = p[i2];
        g_slot[n * 2 + 1] = i2 * NTOK + s2;
        g_sg[n] = 1.f / (1.f + expf(-lg[8]));
    }
}

// ============================================================================
// Merged gate_up GEMM + SiLU*mul  (z=0: shared, z=1..8: expert z-1)
//   A rows from g_xr (pre-rounded); routed rows gathered via g_tok.
//   Output activations stored PRE-ROUNDED to tf32 precision.
//   CTA: 128 rows x 64 cols per half. 256 threads, 8 warps, 2-stage cp.async.
//   SMEM stage: As[128][36], Bg[32][72], Bu[32][72]
// ============================================================================
#define GU_ASZ (128 * 36)
#define GU_BSZ (32 * 72)
#define GU_BUF (GU_ASZ + 2 * GU_BSZ)            // 9216 floats / stage
#define GU_SMEM (2 * GU_BUF * 4)                // 73728 bytes

__global__ __launch_bounds__(256) void gateup_all(const float* __restrict__ Wsh,
                                                  const float* __restrict__ Wex) {
    const int z = blockIdx.z;
    const int m0 = blockIdx.y * 128;
    int F, cnt, ebase = 0;
    const float* W;
    float* actOut;
    if (z == 0) {
        F = ISHA; cnt = NTOK; W = Wsh; actOut = g_acts;
    } else {
        F = IEXP;
        if (blockIdx.x >= IEXP / 64) return;
        const int e = z - 1;
        cnt = g_cnt[e];
        if (m0 >= cnt) return;
        ebase = e * NTOK;
        W = Wex + (size_t)e * HDIM * 2 * IEXP;
        actOut = g_actr + (size_t)e * NTOK * IEXP;
    }
    const int f0 = blockIdx.x * 64;
    const int ldw = 2 * F;
    extern __shared__ float smem[];
    const int tid = threadIdx.x;
    const int wid = tid >> 5, lane = tid & 31;
    const int gid = lane >> 2, tg = lane & 3;
    const int warp_m = (wid & 3) * 32;
    const int warp_n = (wid >> 2) * 32;
    const uint32_t sb = smem_u32(smem);

    // Precompute per-thread staging sources/dests
    const float* aSrc[4];
    uint32_t aOff[4];
#pragma unroll
    for (int i = 0; i < 4; i++) {
        int idx = tid + i * 256;
        int row = idx >> 3, q = idx & 7;
        int t;
        if (z > 0)
            t = g_tok[ebase + ((m0 + row < cnt) ? (m0 + row) : 0)];
        else
            t = m0 + row;
        aSrc[i] = g_xr + (size_t)t * HDIM + q * 4;
        aOff[i] = (uint32_t)(row * 36 + q * 4) * 4;
    }
    const float* bSrc[4];
    uint32_t bOff[4];
#pragma unroll
    for (int i = 0; i < 4; i++) {
        int idx = tid + i * 256;
        int half = idx >> 9;
        int r = (idx >> 4) & 31, q = idx & 15;
        bSrc[i] = W + (size_t)r * ldw + (half ? F + f0 : f0) + q * 4;
        bOff[i] = (uint32_t)(GU_ASZ + half * GU_BSZ + r * 72 + q * 4) * 4;
    }

    float cg[2][4][4], cu[2][4][4];
#pragma unroll
    for (int mf = 0; mf < 2; mf++)
#pragma unroll
        for (int nf = 0; nf < 4; nf++)
#pragma unroll
            for (int r = 0; r < 4; r++) { cg[mf][nf][r] = 0.f; cu[mf][nf][r] = 0.f; }

    // Prologue: stage 0
#pragma unroll
    for (int i = 0; i < 4; i++) cp16(sb + aOff[i], aSrc[i]);
#pragma unroll
    for (int i = 0; i < 4; i++) cp16(sb + bOff[i], bSrc[i]);
    CP_COMMIT();

    int buf = 0;
    const int kIters = HDIM / 32;  // 64
    for (int kt = 0; kt < kIters; kt++) {
        if (kt + 1 < kIters) {
            uint32_t base = sb + ((buf ^ 1) * GU_BUF) * 4;
            const int k0 = (kt + 1) * 32;
#pragma unroll
            for (int i = 0; i < 4; i++) cp16(base + aOff[i], aSrc[i] + k0);
#pragma unroll
            for (int i = 0; i < 4; i++) cp16(base + bOff[i], bSrc[i] + (size_t)k0 * ldw);
            CP_COMMIT();
            CP_WAIT(1);
        } else {
            CP_WAIT(0);
        }
        __syncthreads();

        const float* As = smem + buf * GU_BUF;
        const float* Bg = As + GU_ASZ;
        const float* Bu = Bg + GU_BSZ;
#pragma unroll
        for (int ks = 0; ks < 4; ks++) {
            const int k0 = ks * 8;
            uint32_t a[2][4];
#pragma unroll
            for (int mf = 0; mf < 2; mf++) {   // A pre-rounded: raw bitcast
                int r = warp_m + mf * 16 + gid;
                a[mf][0] = __float_as_uint(As[r * 36 + k0 + tg]);
                a[mf][1] = __float_as_uint(As[(r + 8) * 36 + k0 + tg]);
                a[mf][2] = __float_as_uint(As[r * 36 + k0 + tg + 4]);
                a[mf][3] = __float_as_uint(As[(r + 8) * 36 + k0 + tg + 4]);
            }
#pragma unroll
            for (int nf = 0; nf < 4; nf++) {
                int n = warp_n + nf * 8 + gid;
                uint32_t bg[2], bu[2];
                bg[0] = f2tf32(Bg[(k0 + tg) * 72 + n]);
                bg[1] = f2tf32(Bg[(k0 + tg + 4) * 72 + n]);
                bu[0] = f2tf32(Bu[(k0 + tg) * 72 + n]);
                bu[1] = f2tf32(Bu[(k0 + tg + 4) * 72 + n]);
#pragma unroll
                for (int mf = 0; mf < 2; mf++) {
                    mma8(cg[mf][nf], a[mf], bg);
                    mma8(cu[mf][nf], a[mf], bu);
                }
            }
        }
        __syncthreads();
        buf ^= 1;
    }

    // Epilogue: silu(gate)*up, stored pre-rounded to tf32 precision
#pragma unroll
    for (int mf = 0; mf < 2; mf++) {
        int r0 = m0 + warp_m + mf * 16 + gid;
#pragma unroll
        for (int nf = 0; nf < 4; nf++) {
            int c0 = f0 + warp_n + nf * 8 + 2 * tg;
#pragma unroll
            for (int e = 0; e < 4; e++) {
                int row = r0 + (e >> 1) * 8;
                int col = c0 + (e & 1);
                float gv = cg[mf][nf][e];
                float uv = cu[mf][nf][e];
                float sv = gv / (1.0f + __expf(-gv));
                actOut[(size_t)row * F + col] = __uint_as_float(f2tf32(sv * uv));
            }
        }
    }
}

// ============================================================================
// Merged down GEMM  (z=0: shared -> out directly; z=1..8: expert -> g_eo)
//   A rows pre-rounded (raw bitcast). CTA 128x128, 256 threads, 2-stage.
//   SMEM stage: As[128][36], Bs[32][136]
// ============================================================================
#define DN_ASZ (128 * 36)
#define DN_BSZ (32 * 136)
#define DN_BUF (DN_ASZ + DN_BSZ)                // 8960 floats / stage
#define DN_SMEM (2 * DN_BUF * 4)                // 71680 bytes

__global__ __launch_bounds__(256) void down_all(const float* __restrict__ Wdsh,
                                                const float* __restrict__ Wdex,
                                                float* __restrict__ out) {
    const int z = blockIdx.z;
    const int m0 = blockIdx.y * 128;
    int Fk, cnt, ebase = 0;
    const float* Wd;
    const float* A;
    if (z == 0) {
        Fk = ISHA; cnt = NTOK; Wd = Wdsh; A = g_acts;
    } else {
        Fk = IEXP;
        const int e = z - 1;
        cnt = g_cnt[e];
        if (m0 >= cnt) return;
        ebase = e * NTOK;
        Wd = Wdex + (size_t)e * IEXP * HDIM;
        A = g_actr + (size_t)e * NTOK * IEXP;
    }
    const int n0 = blockIdx.x * 128;
    extern __shared__ float smem[];
    const int tid = threadIdx.x;
    const int wid = tid >> 5, lane = tid & 31;
    const int gid = lane >> 2, tg = lane & 3;
    const int warp_m = (wid & 3) * 32;
    const int warp_n = (wid >> 2) * 64;
    const int kIters = Fk / 32;
    const uint32_t sb = smem_u32(smem);

    const float* aSrc[4];
    uint32_t aOff[4];
#pragma unroll
    for (int i = 0; i < 4; i++) {
        int idx = tid + i * 256;
        int row = idx >> 3, q = idx & 7;
        aSrc[i] = A + (size_t)(m0 + row) * Fk + q * 4;
        aOff[i] = (uint32_t)(row * 36 + q * 4) * 4;
    }
    const float* bSrc[4];
    uint32_t bOff[4];
#pragma unroll
    for (int i = 0; i < 4; i++) {
        int idx = tid + i * 256;
        int r = idx >> 5, q = idx & 31;
        bSrc[i] = Wd + (size_t)r * HDIM + n0 + q * 4;
        bOff[i] = (uint32_t)(DN_ASZ + r * 136 + q * 4) * 4;
    }

    float acc[2][8][4];
#pragma unroll
    for (int mf = 0; mf < 2; mf++)
#pragma unroll
        for (int nf = 0; nf < 8; nf++)
#pragma unroll
            for (int r = 0; r < 4; r++) acc[mf][nf][r] = 0.f;

#pragma unroll
    for (int i = 0; i < 4; i++) cp16(sb + aOff[i], aSrc[i]);
#pragma unroll
    for (int i = 0; i < 4; i++) cp16(sb + bOff[i], bSrc[i]);
    CP_COMMIT();

    int buf = 0;
    for (int kt = 0; kt < kIters; kt++) {
        if (kt + 1 < kIters) {
            uint32_t base = sb + ((buf ^ 1) * DN_BUF) * 4;
            const int k0 = (kt + 1) * 32;
#pragma unroll
            for (int i = 0; i < 4; i++) cp16(base + aOff[i], aSrc[i] + k0);
#pragma unroll
            for (int i = 0; i < 4; i++) cp16(base + bOff[i], bSrc[i] + (size_t)k0 * HDIM);
            CP_COMMIT();
            CP_WAIT(1);
        } else {
            CP_WAIT(0);
        }
        __syncthreads();

        const float* As = smem + buf * DN_BUF;
        const float* Bs = As + DN_ASZ;
#pragma unroll
        for (int ks = 0; ks < 4; ks++) {
            const int k0 = ks * 8;
            uint32_t a[2][4];
#pragma unroll
            for (int mf = 0; mf < 2; mf++) {   // A pre-rounded: raw bitcast
                int r = warp_m + mf * 16 + gid;
                a[mf][0] = __float_as_uint(As[r * 36 + k0 + tg]);
                a[mf][1] = __float_as_uint(As[(r + 8) * 36 + k0 + tg]);
                a[mf][2] = __float_as_uint(As[r * 36 + k0 + tg + 4]);
                a[mf][3] = __float_as_uint(As[(r + 8) * 36 + k0 + tg + 4]);
            }
#pragma unroll
            for (int nf = 0; nf < 8; nf++) {
                int n = warp_n + nf * 8 + gid;
                uint32_t b[2];
                b[0] = f2tf32(Bs[(k0 + tg) * 136 + n]);
                b[1] = f2tf32(Bs[(k0 + tg + 4) * 136 + n]);
#pragma unroll
                for (int mf = 0; mf < 2; mf++) mma8(acc[mf][nf], a[mf], b);
            }
        }
        __syncthreads();
        buf ^= 1;
    }

    // Epilogue
#pragma unroll
    for (int mf = 0; mf < 2; mf++) {
        int r0 = m0 + warp_m + mf * 16 + gid;
#pragma unroll
        for (int h = 0; h < 2; h++) {
            int slot = r0 + h * 8;
            float wv;
            float* orow;
            if (z == 0) {
                wv = g_sg[slot];
                orow = out + (size_t)slot * HDIM;
            } else {
                if (slot >= cnt) continue;
                wv = g_wt[ebase + slot];
                orow = g_eo + (size_t)(ebase + slot) * HDIM;
            }
#pragma unroll
            for (int nf = 0; nf < 8; nf++) {
                int col = n0 + warp_n + nf * 8 + 2 * tg;
                orow[col]     = wv * acc[mf][nf][2 * h];
                orow[col + 1] = wv * acc[mf][nf][2 * h + 1];
            }
        }
    }
}

// ============================================================================
// Combine: out[token] += g_eo[slotA] + g_eo[slotB]   (weights pre-applied)
// ============================================================================
__global__ void combine_kernel(float* __restrict__ out) {
    const int n = blockIdx.x;
    const int tid = threadIdx.x;  // 256
    const size_t r0 = (size_t)g_slot[n * 2] * HDIM;
    const size_t r1 = (size_t)g_slot[n * 2 + 1] * HDIM;
    float4* o = reinterpret_cast<float4*>(out + (size_t)n * HDIM);
    const float4* e0 = reinterpret_cast<const float4*>(g_eo + r0);
    const float4* e1 = reinterpret_cast<const float4*>(g_eo + r1);
#pragma unroll
    for (int i = 0; i < 2; i++) {
        int idx = tid + i * 256;
        float4 v = o[idx], a = e0[idx], b = e1[idx];
        v.x += a.x + b.x; v.y += a.y + b.y;
        v.z += a.z + b.z; v.w += a.w + b.w;
        o[idx] = v;
    }
}

// ============================================================================
// Launch
// ============================================================================
extern "C" void kernel_launch(void* const* d_in, const int* in_sizes, int n_in,
                              void* d_out, int out_size) {
    const float* x = (const float*)d_in[0];       // [1024, 2048]
    const float* gw = (const float*)d_in[1];      // [2048, 8]
    const float* wgu = (const float*)d_in[2];     // [8, 2048, 2816]
    const float* wdn = (const float*)d_in[3];     // [8, 1408, 2048]
    const float* swgu = (const float*)d_in[4];    // [2048, 11264]
    const float* swdn = (const float*)d_in[5];    // [5632, 2048]
    const float* sgw = (const float*)d_in[6];     // [2048, 1]
    float* out = (float*)d_out;                   // [1024, 2048]

    cudaFuncSetAttribute(gateup_all, cudaFuncAttributeMaxDynamicSharedMemorySize, GU_SMEM);
    cudaFuncSetAttribute(down_all, cudaFuncAttributeMaxDynamicSharedMemorySize, DN_SMEM);

    zero_kernel<<<1, 32>>>();
    roundx_kernel<<<(NTOK * HDIM / 4) / 256, 256>>>(x);
    router_kernel<<<NTOK, 128>>>(x, gw, sgw);

    // All gate_up GEMMs (shared z=0 + experts z=1..8) in one launch.
    gateup_all<<<dim3(ISHA / 64, NTOK / 128, 1 + NEXP), 256, GU_SMEM>>>(swgu, wgu);

    // All down GEMMs in one launch: z=0 writes out, z>=1 writes g_eo (disjoint).
    down_all<<<dim3(HDIM / 128, NTOK / 128, 1 + NEXP), 256, DN_SMEM>>>(swdn, wdn, out);

    // Gather the two expert rows per token into out.
    combine_kernel<<<NTOK, 256>>>(out);
}

// round 9
// speedup vs baseline: 2.4354x; 1.0381x over previous
#include <cuda_runtime.h>
#include <cstdint>

// ============================================================================
// Problem constants
// ============================================================================
#define NTOK 1024
#define HDIM 2048
#define NEXP 8
#define IEXP 1408
#define ISHA 5632

// ============================================================================
// Scratch (allocation-free rule: __device__ globals)
// ============================================================================
__device__ float g_xr[(size_t)NTOK * HDIM];            // pre-rounded x (8MB)
__device__ float g_acts[(size_t)NTOK * ISHA];          // shared act (23MB, pre-rounded)
__device__ float g_actr[(size_t)NEXP * NTOK * IEXP];   // routed act (46MB, pre-rounded)
__device__ float g_eo[(size_t)NEXP * NTOK * HDIM];     // routed expert out (67MB)
__device__ float g_sg[NTOK];
__device__ int   g_cnt[NEXP];
__device__ int   g_tok[NEXP * NTOK];                   // expert -> token list
__device__ float g_wt[NEXP * NTOK];                    // expert -> routing weight / slot
__device__ int   g_slot[NTOK * 2];                     // token -> 2 global slots

// ============================================================================
// Helpers
// ============================================================================
__device__ __forceinline__ uint32_t smem_u32(const void* p) {
    uint32_t a;
    asm("{ .reg .u64 t; cvta.to.shared.u64 t, %1; cvt.u32.u64 %0, t; }" : "=r"(a) : "l"(p));
    return a;
}

__device__ __forceinline__ uint32_t f2tf32(float f) {
    uint32_t r;
    asm("cvt.rna.tf32.f32 %0, %1;" : "=r"(r) : "f"(f));
    return r;
}

__device__ __forceinline__ void cp16(uint32_t dst, const float* src) {
    asm volatile("cp.async.cg.shared.global [%0], [%1], 16;" :: "r"(dst), "l"(src));
}
#define CP_COMMIT() asm volatile("cp.async.commit_group;" ::: "memory")
#define CP_WAIT(n)  asm volatile("cp.async.wait_group %0;" :: "n"(n) : "memory")

// m16n8k8 tf32 mma: D += A*B, A row-major (4 regs), B col-major (2 regs)
__device__ __forceinline__ void mma8(float* d, const uint32_t* a, const uint32_t* b) {
    asm volatile(
        "mma.sync.aligned.m16n8k8.row.col.f32.tf32.tf32.f32 "
        "{%0,%1,%2,%3}, {%4,%5,%6,%7}, {%8,%9}, {%0,%1,%2,%3};"
        : "+f"(d[0]), "+f"(d[1]), "+f"(d[2]), "+f"(d[3])
        : "r"(a[0]), "r"(a[1]), "r"(a[2]), "r"(a[3]), "r"(b[0]), "r"(b[1]));
}

// ============================================================================
// Small kernels
// ============================================================================
__global__ void zero_kernel() {
    if (threadIdx.x < NEXP) g_cnt[threadIdx.x] = 0;
}

// Pre-round x to tf32 precision (g_xr). grid 2048 x 256thr, float4 each.
__global__ void roundx_kernel(const float* __restrict__ x) {
    int idx = blockIdx.x * 256 + threadIdx.x;
    float4 v = reinterpret_cast<const float4*>(x)[idx];
    float4 o;
    o.x = __uint_as_float(f2tf32(v.x));
    o.y = __uint_as_float(f2tf32(v.y));
    o.z = __uint_as_float(f2tf32(v.z));
    o.w = __uint_as_float(f2tf32(v.w));
    reinterpret_cast<float4*>(g_xr)[idx] = o;
}

// ============================================================================
// Router: softmax + top-2 -> per-expert token lists + token->slot map
// ============================================================================
__global__ void router_kernel(const float* __restrict__ x,
                              const float* __restrict__ gw,
                              const float* __restrict__ sgw) {
    const int n = blockIdx.x;
    const int tid = threadIdx.x;  // 128
    const float* xr = x + (size_t)n * HDIM;
    float acc[9];
#pragma unroll
    for (int j = 0; j < 9; j++) acc[j] = 0.f;
    for (int k = tid; k < HDIM; k += 128) {
        float xv = xr[k];
#pragma unroll
        for (int e = 0; e < NEXP; e++) acc[e] += xv * gw[k * NEXP + e];
        acc[8] += xv * sgw[k];
    }
    __shared__ float red[9][4];
#pragma unroll
    for (int j = 0; j < 9; j++) {
        float v = acc[j];
#pragma unroll
        for (int o = 16; o > 0; o >>= 1) v += __shfl_xor_sync(0xffffffffu, v, o);
        if ((tid & 31) == 0) red[j][tid >> 5] = v;
    }
    __syncthreads();
    if (tid == 0) {
        float lg[9];
#pragma unroll
        for (int j = 0; j < 9; j++) lg[j] = red[j][0] + red[j][1] + red[j][2] + red[j][3];
        float m = lg[0];
        for (int e = 1; e < NEXP; e++) m = fmaxf(m, lg[e]);
        float p[NEXP], s = 0.f;
        for (int e = 0; e < NEXP; e++) { p[e] = expf(lg[e] - m); s += p[e]; }
        for (int e = 0; e < NEXP; e++) p[e] /= s;
        int i1 = 0;
        for (int e = 1; e < NEXP; e++) if (p[e] > p[i1]) i1 = e;
        int i2 = (i1 == 0) ? 1 : 0;
        for (int e = 0; e < NEXP; e++) if (e != i1 && p[e] > p[i2]) i2 = e;
        int s1 = atomicAdd(&g_cnt[i1], 1);
        g_tok[i1 * NTOK + s1] = n;  g_wt[i1 * NTOK + s1] = p[i1];
        g_slot[n * 2] = i1 * NTOK + s1;
        int s2 = atomicAdd(&g_cnt[i2], 1);
        g_tok[i2 * NTOK + s2] = n;  g_wt[i2 * NTOK + s2] = p[i2];
        g_slot[n * 2 + 1] = i2 * NTOK + s2;
        g_sg[n] = 1.f / (1.f + expf(-lg[8]));
    }
}

// ============================================================================
// Merged gate_up GEMM + SiLU*mul  (z=0: shared, z=1..8: expert z-1)
//   CTA: 128 rows x 32 cols per half (gate+up). 256 threads, 8 warps (4m x 2n),
//   warp tile 32m x 16n per half. acc = 32 regs/thread -> 3 CTAs/SM.
//   SMEM stage: As[128][36], B[2][32][40]
// ============================================================================
#define GU_ASZ (128 * 36)
#define GU_BSZ (32 * 40)
#define GU_BUF (GU_ASZ + 2 * GU_BSZ)            // 7168 floats / stage
#define GU_SMEM (2 * GU_BUF * 4)                // 57344 bytes

__global__ __launch_bounds__(256, 3) void gateup_all(const float* __restrict__ Wsh,
                                                     const float* __restrict__ Wex) {
    const int z = blockIdx.z;
    const int m0 = blockIdx.y * 128;
    int F, cnt, ebase = 0;
    const float* W;
    float* actOut;
    if (z == 0) {
        F = ISHA; cnt = NTOK; W = Wsh; actOut = g_acts;
    } else {
        F = IEXP;
        if (blockIdx.x >= IEXP / 32) return;
        const int e = z - 1;
        cnt = g_cnt[e];
        if (m0 >= cnt) return;
        ebase = e * NTOK;
        W = Wex + (size_t)e * HDIM * 2 * IEXP;
        actOut = g_actr + (size_t)e * NTOK * IEXP;
    }
    const int f0 = blockIdx.x * 32;
    const int ldw = 2 * F;
    extern __shared__ float smem[];
    const int tid = threadIdx.x;
    const int wid = tid >> 5, lane = tid & 31;
    const int gid = lane >> 2, tg = lane & 3;
    const int warp_m = (wid & 3) * 32;
    const int warp_n = (wid >> 2) * 16;
    const uint32_t sb = smem_u32(smem);

    // Per-thread staging: A 4 x cp16, B 2 x cp16
    const float* aSrc[4];
    uint32_t aOff[4];
#pragma unroll
    for (int i = 0; i < 4; i++) {
        int idx = tid + i * 256;
        int row = idx >> 3, q = idx & 7;
        int t;
        if (z > 0)
            t = g_tok[ebase + ((m0 + row < cnt) ? (m0 + row) : 0)];
        else
            t = m0 + row;
        aSrc[i] = g_xr + (size_t)t * HDIM + q * 4;
        aOff[i] = (uint32_t)(row * 36 + q * 4) * 4;
    }
    const float* bSrc[2];
    uint32_t bOff[2];
#pragma unroll
    for (int i = 0; i < 2; i++) {
        int idx = tid + i * 256;
        int half = idx >> 8;
        int r = (idx >> 3) & 31, q = idx & 7;
        bSrc[i] = W + (size_t)r * ldw + (half ? F + f0 : f0) + q * 4;
        bOff[i] = (uint32_t)(GU_ASZ + half * GU_BSZ + r * 40 + q * 4) * 4;
    }

    float c[2][2][2][4];   // [half][mf][nf][e]
#pragma unroll
    for (int h = 0; h < 2; h++)
#pragma unroll
        for (int mf = 0; mf < 2; mf++)
#pragma unroll
            for (int nf = 0; nf < 2; nf++)
#pragma unroll
                for (int r = 0; r < 4; r++) c[h][mf][nf][r] = 0.f;

    // Prologue: stage 0
#pragma unroll
    for (int i = 0; i < 4; i++) cp16(sb + aOff[i], aSrc[i]);
#pragma unroll
    for (int i = 0; i < 2; i++) cp16(sb + bOff[i], bSrc[i]);
    CP_COMMIT();

    int buf = 0;
    const int kIters = HDIM / 32;  // 64
    for (int kt = 0; kt < kIters; kt++) {
        if (kt + 1 < kIters) {
            uint32_t base = sb + ((buf ^ 1) * GU_BUF) * 4;
            const int k0 = (kt + 1) * 32;
#pragma unroll
            for (int i = 0; i < 4; i++) cp16(base + aOff[i], aSrc[i] + k0);
#pragma unroll
            for (int i = 0; i < 2; i++) cp16(base + bOff[i], bSrc[i] + (size_t)k0 * ldw);
            CP_COMMIT();
            CP_WAIT(1);
        } else {
            CP_WAIT(0);
        }
        __syncthreads();

        const float* As = smem + buf * GU_BUF;
        const float* B0 = As + GU_ASZ;
#pragma unroll
        for (int ks = 0; ks < 4; ks++) {
            const int k0 = ks * 8;
            uint32_t a[2][4];
#pragma unroll
            for (int mf = 0; mf < 2; mf++) {   // A pre-rounded: raw bitcast
                int r = warp_m + mf * 16 + gid;
                a[mf][0] = __float_as_uint(As[r * 36 + k0 + tg]);
                a[mf][1] = __float_as_uint(As[(r + 8) * 36 + k0 + tg]);
                a[mf][2] = __float_as_uint(As[r * 36 + k0 + tg + 4]);
                a[mf][3] = __float_as_uint(As[(r + 8) * 36 + k0 + tg + 4]);
            }
#pragma unroll
            for (int h = 0; h < 2; h++) {
                const float* Bs = B0 + h * GU_BSZ;
#pragma unroll
                for (int nf = 0; nf < 2; nf++) {
                    int n = warp_n + nf * 8 + gid;
                    uint32_t b[2];
                    b[0] = f2tf32(Bs[(k0 + tg) * 40 + n]);
                    b[1] = f2tf32(Bs[(k0 + tg + 4) * 40 + n]);
#pragma unroll
                    for (int mf = 0; mf < 2; mf++) mma8(c[h][mf][nf], a[mf], b);
                }
            }
        }
        __syncthreads();
        buf ^= 1;
    }

    // Epilogue: silu(gate)*up, stored pre-rounded to tf32 precision
#pragma unroll
    for (int mf = 0; mf < 2; mf++) {
        int r0 = m0 + warp_m + mf * 16 + gid;
#pragma unroll
        for (int nf = 0; nf < 2; nf++) {
            int c0 = f0 + warp_n + nf * 8 + 2 * tg;
#pragma unroll
            for (int e = 0; e < 4; e++) {
                int row = r0 + (e >> 1) * 8;
                int col = c0 + (e & 1);
                float gv = c[0][mf][nf][e];
                float uv = c[1][mf][nf][e];
                float sv = gv / (1.0f + __expf(-gv));
                actOut[(size_t)row * F + col] = __uint_as_float(f2tf32(sv * uv));
            }
        }
    }
}

// ============================================================================
// Merged down GEMM  (z=0: shared -> out; z=1..8: expert -> g_eo)
//   CTA 128m x 64n, 256 threads, 8 warps (4m x 2n), warp tile 32x32.
//   acc = 32 regs/thread -> 3 CTAs/SM. SMEM stage: As[128][36], Bs[32][72]
// ============================================================================
#define DN_ASZ (128 * 36)
#define DN_BSZ (32 * 72)
#define DN_BUF (DN_ASZ + DN_BSZ)                // 6912 floats / stage
#define DN_SMEM (2 * DN_BUF * 4)                // 55296 bytes

__global__ __launch_bounds__(256, 3) void down_all(const float* __restrict__ Wdsh,
                                                   const float* __restrict__ Wdex,
                                                   float* __restrict__ out) {
    const int z = blockIdx.z;
    const int m0 = blockIdx.y * 128;
    int Fk, cnt, ebase = 0;
    const float* Wd;
    const float* A;
    if (z == 0) {
        Fk = ISHA; cnt = NTOK; Wd = Wdsh; A = g_acts;
    } else {
        Fk = IEXP;
        const int e = z - 1;
        cnt = g_cnt[e];
        if (m0 >= cnt) return;
        ebase = e * NTOK;
        Wd = Wdex + (size_t)e * IEXP * HDIM;
        A = g_actr + (size_t)e * NTOK * IEXP;
    }
    const int n0 = blockIdx.x * 64;
    extern __shared__ float smem[];
    const int tid = threadIdx.x;
    const int wid = tid >> 5, lane = tid & 31;
    const int gid = lane >> 2, tg = lane & 3;
    const int warp_m = (wid & 3) * 32;
    const int warp_n = (wid >> 2) * 32;
    const int kIters = Fk / 32;
    const uint32_t sb = smem_u32(smem);

    const float* aSrc[4];
    uint32_t aOff[4];
#pragma unroll
    for (int i = 0; i < 4; i++) {
        int idx = tid + i * 256;
        int row = idx >> 3, q = idx & 7;
        aSrc[i] = A + (size_t)(m0 + row) * Fk + q * 4;
        aOff[i] = (uint32_t)(row * 36 + q * 4) * 4;
    }
    const float* bSrc[2];
    uint32_t bOff[2];
#pragma unroll
    for (int i = 0; i < 2; i++) {
        int idx = tid + i * 256;
        int r = idx >> 4, q = idx & 15;
        bSrc[i] = Wd + (size_t)r * HDIM + n0 + q * 4;
        bOff[i] = (uint32_t)(DN_ASZ + r * 72 + q * 4) * 4;
    }

    float acc[2][4][4];
#pragma unroll
    for (int mf = 0; mf < 2; mf++)
#pragma unroll
        for (int nf = 0; nf < 4; nf++)
#pragma unroll
            for (int r = 0; r < 4; r++) acc[mf][nf][r] = 0.f;

#pragma unroll
    for (int i = 0; i < 4; i++) cp16(sb + aOff[i], aSrc[i]);
#pragma unroll
    for (int i = 0; i < 2; i++) cp16(sb + bOff[i], bSrc[i]);
    CP_COMMIT();

    int buf = 0;
    for (int kt = 0; kt < kIters; kt++) {
        if (kt + 1 < kIters) {
            uint32_t base = sb + ((buf ^ 1) * DN_BUF) * 4;
            const int k0 = (kt + 1) * 32;
#pragma unroll
            for (int i = 0; i < 4; i++) cp16(base + aOff[i], aSrc[i] + k0);
#pragma unroll
            for (int i = 0; i < 2; i++) cp16(base + bOff[i], bSrc[i] + (size_t)k0 * HDIM);
            CP_COMMIT();
            CP_WAIT(1);
        } else {
            CP_WAIT(0);
        }
        __syncthreads();

        const float* As = smem + buf * DN_BUF;
        const float* Bs = As + DN_ASZ;
#pragma unroll
        for (int ks = 0; ks < 4; ks++) {
            const int k0 = ks * 8;
            uint32_t a[2][4];
#pragma unroll
            for (int mf = 0; mf < 2; mf++) {   // A pre-rounded: raw bitcast
                int r = warp_m + mf * 16 + gid;
                a[mf][0] = __float_as_uint(As[r * 36 + k0 + tg]);
                a[mf][1] = __float_as_uint(As[(r + 8) * 36 + k0 + tg]);
                a[mf][2] = __float_as_uint(As[r * 36 + k0 + tg + 4]);
                a[mf][3] = __float_as_uint(As[(r + 8) * 36 + k0 + tg + 4]);
            }
#pragma unroll
            for (int nf = 0; nf < 4; nf++) {
                int n = warp_n + nf * 8 + gid;
                uint32_t b[2];
                b[0] = f2tf32(Bs[(k0 + tg) * 72 + n]);
                b[1] = f2tf32(Bs[(k0 + tg + 4) * 72 + n]);
#pragma unroll
                for (int mf = 0; mf < 2; mf++) mma8(acc[mf][nf], a[mf], b);
            }
        }
        __syncthreads();
        buf ^= 1;
    }

    // Epilogue
#pragma unroll
    for (int mf = 0; mf < 2; mf++) {
        int r0 = m0 + warp_m + mf * 16 + gid;
#pragma unroll
        for (int h = 0; h < 2; h++) {
            int slot = r0 + h * 8;
            float wv;
            float* orow;
            if (z == 0) {
                wv = g_sg[slot];
                orow = out + (size_t)slot * HDIM;
            } else {
                if (slot >= cnt) continue;
                wv = g_wt[ebase + slot];
                orow = g_eo + (size_t)(ebase + slot) * HDIM;
            }
#pragma unroll
            for (int nf = 0; nf < 4; nf++) {
                int col = n0 + warp_n + nf * 8 + 2 * tg;
                orow[col]     = wv * acc[mf][nf][2 * h];
                orow[col + 1] = wv * acc[mf][nf][2 * h + 1];
            }
        }
    }
}

// ============================================================================
// Combine: out[token] += g_eo[slotA] + g_eo[slotB]   (weights pre-applied)
// ============================================================================
__global__ void combine_kernel(float* __restrict__ out) {
    const int n = blockIdx.x;
    const int tid = threadIdx.x;  // 256
    const size_t r0 = (size_t)g_slot[n * 2] * HDIM;
    const size_t r1 = (size_t)g_slot[n * 2 + 1] * HDIM;
    float4* o = reinterpret_cast<float4*>(out + (size_t)n * HDIM);
    const float4* e0 = reinterpret_cast<const float4*>(g_eo + r0);
    const float4* e1 = reinterpret_cast<const float4*>(g_eo + r1);
#pragma unroll
    for (int i = 0; i < 2; i++) {
        int idx = tid + i * 256;
        float4 v = o[idx], a = e0[idx], b = e1[idx];
        v.x += a.x + b.x; v.y += a.y + b.y;
        v.z += a.z + b.z; v.w += a.w + b.w;
        o[idx] = v;
    }
}

// ============================================================================
// Launch
// ============================================================================
extern "C" void kernel_launch(void* const* d_in, const int* in_sizes, int n_in,
                              void* d_out, int out_size) {
    const float* x = (const float*)d_in[0];       // [1024, 2048]
    const float* gw = (const float*)d_in[1];      // [2048, 8]
    const float* wgu = (const float*)d_in[2];     // [8, 2048, 2816]
    const float* wdn = (const float*)d_in[3];     // [8, 1408, 2048]
    const float* swgu = (const float*)d_in[4];    // [2048, 11264]
    const float* swdn = (const float*)d_in[5];    // [5632, 2048]
    const float* sgw = (const float*)d_in[6];     // [2048, 1]
    float* out = (float*)d_out;                   // [1024, 2048]

    cudaFuncSetAttribute(gateup_all, cudaFuncAttributeMaxDynamicSharedMemorySize, GU_SMEM);
    cudaFuncSetAttribute(down_all, cudaFuncAttributeMaxDynamicSharedMemorySize, DN_SMEM);

    zero_kernel<<<1, 32>>>();
    roundx_kernel<<<(NTOK * HDIM / 4) / 256, 256>>>(x);
    router_kernel<<<NTOK, 128>>>(x, gw, sgw);

    // All gate_up GEMMs (shared z=0 + experts z=1..8) in one launch.
    gateup_all<<<dim3(ISHA / 32, NTOK / 128, 1 + NEXP), 256, GU_SMEM>>>(swgu, wgu);

    // All down GEMMs in one launch: z=0 writes out, z>=1 writes g_eo (disjoint).
    down_all<<<dim3(HDIM / 64, NTOK / 128, 1 + NEXP), 256, DN_SMEM>>>(swdn, wdn, out);

    // Gather the two expert rows per token into out.
    combine_kernel<<<NTOK, 256>>>(out);
}

// round 10
// speedup vs baseline: 2.4693x; 1.0139x over previous
#include <cuda_runtime.h>
#include <cstdint>

// ============================================================================
// Problem constants
// ============================================================================
#define NTOK 1024
#define HDIM 2048
#define NEXP 8
#define IEXP 1408
#define ISHA 5632

// ============================================================================
// Scratch (allocation-free rule: __device__ globals)
// ============================================================================
__device__ float g_xr[(size_t)NTOK * HDIM];            // pre-rounded x (8MB)
__device__ float g_acts[(size_t)NTOK * ISHA];          // shared act (23MB, pre-rounded)
__device__ float g_actr[(size_t)NEXP * NTOK * IEXP];   // routed act (46MB, pre-rounded)
__device__ float g_eo[(size_t)NEXP * NTOK * HDIM];     // routed expert out (67MB)
__device__ float g_sg[NTOK];
__device__ int   g_cnt[NEXP];
__device__ int   g_tok[NEXP * NTOK];                   // expert -> token list
__device__ float g_wt[NEXP * NTOK];                    // expert -> routing weight / slot
__device__ int   g_slot[NTOK * 2];                     // token -> 2 global slots

// ============================================================================
// Helpers
// ============================================================================
__device__ __forceinline__ uint32_t smem_u32(const void* p) {
    uint32_t a;
    asm("{ .reg .u64 t; cvta.to.shared.u64 t, %1; cvt.u32.u64 %0, t; }" : "=r"(a) : "l"(p));
    return a;
}

__device__ __forceinline__ uint32_t f2tf32(float f) {
    uint32_t r;
    asm("cvt.rna.tf32.f32 %0, %1;" : "=r"(r) : "f"(f));
    return r;
}

__device__ __forceinline__ void cp16(uint32_t dst, const float* src) {
    asm volatile("cp.async.cg.shared.global [%0], [%1], 16;" :: "r"(dst), "l"(src));
}
#define CP_COMMIT() asm volatile("cp.async.commit_group;" ::: "memory")
#define CP_WAIT(n)  asm volatile("cp.async.wait_group %0;" :: "n"(n) : "memory")

// m16n8k8 tf32 mma: D += A*B, A row-major (4 regs), B col-major (2 regs)
__device__ __forceinline__ void mma8(float* d, const uint32_t* a, const uint32_t* b) {
    asm volatile(
        "mma.sync.aligned.m16n8k8.row.col.f32.tf32.tf32.f32 "
        "{%0,%1,%2,%3}, {%4,%5,%6,%7}, {%8,%9}, {%0,%1,%2,%3};"
        : "+f"(d[0]), "+f"(d[1]), "+f"(d[2]), "+f"(d[3])
        : "r"(a[0]), "r"(a[1]), "r"(a[2]), "r"(a[3]), "r"(b[0]), "r"(b[1]));
}

// ============================================================================
// Small kernels
// ============================================================================
__global__ void zero_kernel() {
    if (threadIdx.x < NEXP) g_cnt[threadIdx.x] = 0;
}

// Pre-round x to tf32 precision (g_xr).
__global__ void roundx_kernel(const float* __restrict__ x) {
    int idx = blockIdx.x * 256 + threadIdx.x;
    float4 v = reinterpret_cast<const float4*>(x)[idx];
    float4 o;
    o.x = __uint_as_float(f2tf32(v.x));
    o.y = __uint_as_float(f2tf32(v.y));
    o.z = __uint_as_float(f2tf32(v.z));
    o.w = __uint_as_float(f2tf32(v.w));
    reinterpret_cast<float4*>(g_xr)[idx] = o;
}

// ============================================================================
// Router: softmax + top-2 -> per-expert token lists + token->slot map
// ============================================================================
__global__ void router_kernel(const float* __restrict__ x,
                              const float* __restrict__ gw,
                              const float* __restrict__ sgw) {
    const int n = blockIdx.x;
    const int tid = threadIdx.x;  // 128
    const float* xr = x + (size_t)n * HDIM;
    float acc[9];
#pragma unroll
    for (int j = 0; j < 9; j++) acc[j] = 0.f;
    for (int k = tid; k < HDIM; k += 128) {
        float xv = xr[k];
#pragma unroll
        for (int e = 0; e < NEXP; e++) acc[e] += xv * gw[k * NEXP + e];
        acc[8] += xv * sgw[k];
    }
    __shared__ float red[9][4];
#pragma unroll
    for (int j = 0; j < 9; j++) {
        float v = acc[j];
#pragma unroll
        for (int o = 16; o > 0; o >>= 1) v += __shfl_xor_sync(0xffffffffu, v, o);
        if ((tid & 31) == 0) red[j][tid >> 5] = v;
    }
    __syncthreads();
    if (tid == 0) {
        float lg[9];
#pragma unroll
        for (int j = 0; j < 9; j++) lg[j] = red[j][0] + red[j][1] + red[j][2] + red[j][3];
        float m = lg[0];
        for (int e = 1; e < NEXP; e++) m = fmaxf(m, lg[e]);
        float p[NEXP], s = 0.f;
        for (int e = 0; e < NEXP; e++) { p[e] = expf(lg[e] - m); s += p[e]; }
        for (int e = 0; e < NEXP; e++) p[e] /= s;
        int i1 = 0;
        for (int e = 1; e < NEXP; e++) if (p[e] > p[i1]) i1 = e;
        int i2 = (i1 == 0) ? 1 : 0;
        for (int e = 0; e < NEXP; e++) if (e != i1 && p[e] > p[i2]) i2 = e;
        int s1 = atomicAdd(&g_cnt[i1], 1);
        g_tok[i1 * NTOK + s1] = n;  g_wt[i1 * NTOK + s1] = p[i1];
        g_slot[n * 2] = i1 * NTOK + s1;
        int s2 = atomicAdd(&g_cnt[i2], 1);
        g_tok[i2 * NTOK + s2] = n;  g_wt[i2 * NTOK + s2] = p[i2];
        g_slot[n * 2 + 1] = i2 * NTOK + s2;
        g_sg[n] = 1.f / (1.f + expf(-lg[8]));
    }
}

// ============================================================================
// Merged gate_up GEMM + SiLU*mul  (z=0: shared, z=1..8: expert z-1)
//   CTA: 128m x 64f. 128 threads, 4 warps, each 64m x 64n:
//     wid&1 -> m-half, wid>>1 -> gate(0)/up(1).
//   acc = 128 regs/thread, LDS/MMA = 1.0. 3 CTAs/SM.
//   SMEM stage: As[128][36], Bg[32][72], Bu[32][72]. Epilogue: up warps
//   exchange acc through (reused) stage smem, gate warps combine silu*mul.
// ============================================================================
#define GU_ASZ (128 * 36)
#define GU_BSZ (32 * 72)
#define GU_BUF (GU_ASZ + 2 * GU_BSZ)            // 9216 floats / stage
#define GU_SMEM (2 * GU_BUF * 4)                // 73728 bytes

__global__ __launch_bounds__(128, 3) void gateup_all(const float* __restrict__ Wsh,
                                                     const float* __restrict__ Wex) {
    const int z = blockIdx.z;
    const int m0 = blockIdx.y * 128;
    int F, cnt, ebase = 0;
    const float* W;
    float* actOut;
    if (z == 0) {
        F = ISHA; cnt = NTOK; W = Wsh; actOut = g_acts;
    } else {
        F = IEXP;
        if (blockIdx.x >= IEXP / 64) return;
        const int e = z - 1;
        cnt = g_cnt[e];
        if (m0 >= cnt) return;
        ebase = e * NTOK;
        W = Wex + (size_t)e * HDIM * 2 * IEXP;
        actOut = g_actr + (size_t)e * NTOK * IEXP;
    }
    const int f0 = blockIdx.x * 64;
    const int ldw = 2 * F;
    extern __shared__ float smem[];
    const int tid = threadIdx.x;
    const int wid = tid >> 5, lane = tid & 31;
    const int gid = lane >> 2, tg = lane & 3;
    const int wm = (wid & 1) * 64;       // m-half
    const int uphalf = wid >> 1;         // 0 = gate, 1 = up
    const uint32_t sb = smem_u32(smem);

    // ---- staging addressing (linear) ----
    // A: i=0..7: row = (tid>>3) + 16*i, q = tid&7
    const int aRow0 = tid >> 3, aQ = tid & 7;
    uint32_t aByte[8];                    // token row byte offsets into g_xr
#pragma unroll
    for (int i = 0; i < 8; i++) {
        int row = aRow0 + 16 * i;
        int t;
        if (z > 0)
            t = g_tok[ebase + ((m0 + row < cnt) ? (m0 + row) : 0)];
        else
            t = m0 + row;
        aByte[i] = (uint32_t)t * (HDIM * 4);
    }
    const char* xbase = (const char*)g_xr + aQ * 16;
    const uint32_t aDst0 = sb + (uint32_t)(aRow0 * 36 + aQ * 4) * 4;
    // B: i=0..7: half = i>>2, r = (tid>>4) + 8*(i&3), q = tid&15
    const int bR0 = tid >> 4, bQ = tid & 15;
    const float* bBase = W + (size_t)bR0 * ldw + f0 + bQ * 4;
    const uint32_t bDst0 = sb + (uint32_t)(GU_ASZ + bR0 * 72 + bQ * 4) * 4;

    float acc[4][8][4];
#pragma unroll
    for (int mf = 0; mf < 4; mf++)
#pragma unroll
        for (int nf = 0; nf < 8; nf++)
#pragma unroll
            for (int r = 0; r < 4; r++) acc[mf][nf][r] = 0.f;

    // ---- prologue: stage 0 ----
#pragma unroll
    for (int i = 0; i < 8; i++)
        cp16(aDst0 + (uint32_t)(i * 16 * 36 * 4),
             (const float*)(xbase + aByte[i]));
#pragma unroll
    for (int i = 0; i < 8; i++) {
        int half = i >> 2, rr = i & 3;
        cp16(bDst0 + (uint32_t)((half * GU_BSZ + rr * 8 * 72) * 4),
             bBase + (size_t)(half ? F : 0) + (size_t)(rr * 8) * ldw);
    }
    CP_COMMIT();

    int buf = 0;
    const int kIters = HDIM / 32;  // 64
    for (int kt = 0; kt < kIters; kt++) {
        if (kt + 1 < kIters) {
            const uint32_t bufOff = (uint32_t)(((buf ^ 1) * GU_BUF) * 4);
            const int k0 = (kt + 1) * 32;
#pragma unroll
            for (int i = 0; i < 8; i++)
                cp16(aDst0 + bufOff + (uint32_t)(i * 16 * 36 * 4),
                     (const float*)(xbase + aByte[i]) + k0);
#pragma unroll
            for (int i = 0; i < 8; i++) {
                int half = i >> 2, rr = i & 3;
                cp16(bDst0 + bufOff + (uint32_t)((half * GU_BSZ + rr * 8 * 72) * 4),
                     bBase + (size_t)(half ? F : 0) + (size_t)(k0 + rr * 8) * ldw);
            }
            CP_COMMIT();
            CP_WAIT(1);
        } else {
            CP_WAIT(0);
        }
        __syncthreads();

        const float* As = smem + buf * GU_BUF;
        const float* Bs = As + GU_ASZ + uphalf * GU_BSZ;
#pragma unroll
        for (int ks = 0; ks < 4; ks++) {
            const int k0 = ks * 8;
            uint32_t a[4][4];
#pragma unroll
            for (int mf = 0; mf < 4; mf++) {   // A pre-rounded: raw bitcast
                int r = wm + mf * 16 + gid;
                a[mf][0] = __float_as_uint(As[r * 36 + k0 + tg]);
                a[mf][1] = __float_as_uint(As[(r + 8) * 36 + k0 + tg]);
                a[mf][2] = __float_as_uint(As[r * 36 + k0 + tg + 4]);
                a[mf][3] = __float_as_uint(As[(r + 8) * 36 + k0 + tg + 4]);
            }
#pragma unroll
            for (int nf = 0; nf < 8; nf++) {
                int n = nf * 8 + gid;
                uint32_t b[2];
                b[0] = f2tf32(Bs[(k0 + tg) * 72 + n]);
                b[1] = f2tf32(Bs[(k0 + tg + 4) * 72 + n]);
#pragma unroll
                for (int mf = 0; mf < 4; mf++) mma8(acc[mf][nf], a[mf], b);
            }
        }
        __syncthreads();
        buf ^= 1;
    }

    // ---- epilogue: exchange up through smem, gate warps combine ----
    // ex[m][72], m = 0..127 (reuses stage memory; mainloop fully drained)
    if (uphalf) {
#pragma unroll
        for (int mf = 0; mf < 4; mf++)
#pragma unroll
            for (int h = 0; h < 2; h++) {
                int row = wm + mf * 16 + gid + h * 8;
#pragma unroll
                for (int nf = 0; nf < 8; nf++) {
                    int col = nf * 8 + 2 * tg;
                    smem[row * 72 + col]     = acc[mf][nf][2 * h];
                    smem[row * 72 + col + 1] = acc[mf][nf][2 * h + 1];
                }
            }
    }
    __syncthreads();
    if (!uphalf) {
#pragma unroll
        for (int mf = 0; mf < 4; mf++)
#pragma unroll
            for (int h = 0; h < 2; h++) {
                int row = wm + mf * 16 + gid + h * 8;
                float* orow = actOut + (size_t)(m0 + row) * F + f0;
#pragma unroll
                for (int nf = 0; nf < 8; nf++) {
                    int col = nf * 8 + 2 * tg;
                    float g0 = acc[mf][nf][2 * h];
                    float g1 = acc[mf][nf][2 * h + 1];
                    float u0 = smem[row * 72 + col];
                    float u1 = smem[row * 72 + col + 1];
                    float s0 = g0 / (1.0f + __expf(-g0));
                    float s1 = g1 / (1.0f + __expf(-g1));
                    orow[col]     = __uint_as_float(f2tf32(s0 * u0));
                    orow[col + 1] = __uint_as_float(f2tf32(s1 * u1));
                }
            }
    }
}

// ============================================================================
// Merged down GEMM  (z=0: shared -> out; z=1..8: expert -> g_eo)
//   CTA 128m x 128n. 128 threads, 4 warps, each 64m x 64n.
//   acc = 128 regs/thread, 3 CTAs/SM. SMEM stage: As[128][36], Bs[32][136]
// ============================================================================
#define DN_ASZ (128 * 36)
#define DN_BSZ (32 * 136)
#define DN_BUF (DN_ASZ + DN_BSZ)                // 8960 floats / stage
#define DN_SMEM (2 * DN_BUF * 4)                // 71680 bytes

__global__ __launch_bounds__(128, 3) void down_all(const float* __restrict__ Wdsh,
                                                   const float* __restrict__ Wdex,
                                                   float* __restrict__ out) {
    const int z = blockIdx.z;
    const int m0 = blockIdx.y * 128;
    int Fk, cnt, ebase = 0;
    const float* Wd;
    const float* A;
    if (z == 0) {
        Fk = ISHA; cnt = NTOK; Wd = Wdsh; A = g_acts;
    } else {
        Fk = IEXP;
        const int e = z - 1;
        cnt = g_cnt[e];
        if (m0 >= cnt) return;
        ebase = e * NTOK;
        Wd = Wdex + (size_t)e * IEXP * HDIM;
        A = g_actr + (size_t)e * NTOK * IEXP;
    }
    const int n0 = blockIdx.x * 128;
    extern __shared__ float smem[];
    const int tid = threadIdx.x;
    const int wid = tid >> 5, lane = tid & 31;
    const int gid = lane >> 2, tg = lane & 3;
    const int wm = (wid & 1) * 64;
    const int wn = (wid >> 1) * 64;
    const int kIters = Fk / 32;
    const uint32_t sb = smem_u32(smem);

    // A: i=0..7: row = (tid>>3) + 16*i, q = tid&7 (rows linear: slot space)
    const int aRow0 = tid >> 3, aQ = tid & 7;
    const float* aBase = A + (size_t)(m0 + aRow0) * Fk + aQ * 4;
    const size_t aStride = (size_t)16 * Fk;
    const uint32_t aDst0 = sb + (uint32_t)(aRow0 * 36 + aQ * 4) * 4;
    // B: i=0..7: r = (tid>>5) + 4*i, q = tid&31
    const int bR0 = tid >> 5, bQ = tid & 31;
    const float* bBase = Wd + (size_t)bR0 * HDIM + n0 + bQ * 4;
    const uint32_t bDst0 = sb + (uint32_t)(DN_ASZ + bR0 * 136 + bQ * 4) * 4;

    float acc[4][8][4];
#pragma unroll
    for (int mf = 0; mf < 4; mf++)
#pragma unroll
        for (int nf = 0; nf < 8; nf++)
#pragma unroll
            for (int r = 0; r < 4; r++) acc[mf][nf][r] = 0.f;

#pragma unroll
    for (int i = 0; i < 8; i++)
        cp16(aDst0 + (uint32_t)(i * 16 * 36 * 4), aBase + (size_t)i * aStride);
#pragma unroll
    for (int i = 0; i < 8; i++)
        cp16(bDst0 + (uint32_t)(i * 4 * 136 * 4), bBase + (size_t)(i * 4) * HDIM);
    CP_COMMIT();

    int buf = 0;
    for (int kt = 0; kt < kIters; kt++) {
        if (kt + 1 < kIters) {
            const uint32_t bufOff = (uint32_t)(((buf ^ 1) * DN_BUF) * 4);
            const int k0 = (kt + 1) * 32;
#pragma unroll
            for (int i = 0; i < 8; i++)
                cp16(aDst0 + bufOff + (uint32_t)(i * 16 * 36 * 4),
                     aBase + (size_t)i * aStride + k0);
#pragma unroll
            for (int i = 0; i < 8; i++)
                cp16(bDst0 + bufOff + (uint32_t)(i * 4 * 136 * 4),
                     bBase + (size_t)(k0 + i * 4) * HDIM);
            CP_COMMIT();
            CP_WAIT(1);
        } else {
            CP_WAIT(0);
        }
        __syncthreads();

        const float* As = smem + buf * DN_BUF;
        const float* Bs = As + DN_ASZ;
#pragma unroll
        for (int ks = 0; ks < 4; ks++) {
            const int k0 = ks * 8;
            uint32_t a[4][4];
#pragma unroll
            for (int mf = 0; mf < 4; mf++) {   // A pre-rounded: raw bitcast
                int r = wm + mf * 16 + gid;
                a[mf][0] = __float_as_uint(As[r * 36 + k0 + tg]);
                a[mf][1] = __float_as_uint(As[(r + 8) * 36 + k0 + tg]);
                a[mf][2] = __float_as_uint(As[r * 36 + k0 + tg + 4]);
                a[mf][3] = __float_as_uint(As[(r + 8) * 36 + k0 + tg + 4]);
            }
#pragma unroll
            for (int nf = 0; nf < 8; nf++) {
                int n = wn + nf * 8 + gid;
                uint32_t b[2];
                b[0] = f2tf32(Bs[(k0 + tg) * 136 + n]);
                b[1] = f2tf32(Bs[(k0 + tg + 4) * 136 + n]);
#pragma unroll
                for (int mf = 0; mf < 4; mf++) mma8(acc[mf][nf], a[mf], b);
            }
        }
        __syncthreads();
        buf ^= 1;
    }

    // Epilogue
#pragma unroll
    for (int mf = 0; mf < 4; mf++) {
#pragma unroll
        for (int h = 0; h < 2; h++) {
            int slot = m0 + wm + mf * 16 + gid + h * 8;
            float wv;
            float* orow;
            if (z == 0) {
                wv = g_sg[slot];
                orow = out + (size_t)slot * HDIM;
            } else {
                if (slot >= cnt) continue;
                wv = g_wt[ebase + slot];
                orow = g_eo + (size_t)(ebase + slot) * HDIM;
            }
#pragma unroll
            for (int nf = 0; nf < 8; nf++) {
                int col = n0 + wn + nf * 8 + 2 * tg;
                orow[col]     = wv * acc[mf][nf][2 * h];
                orow[col + 1] = wv * acc[mf][nf][2 * h + 1];
            }
        }
    }
}

// ============================================================================
// Combine: out[token] += g_eo[slotA] + g_eo[slotB]   (weights pre-applied)
// ============================================================================
__global__ void combine_kernel(float* __restrict__ out) {
    const int n = blockIdx.x;
    const int tid = threadIdx.x;  // 256
    const size_t r0 = (size_t)g_slot[n * 2] * HDIM;
    const size_t r1 = (size_t)g_slot[n * 2 + 1] * HDIM;
    float4* o = reinterpret_cast<float4*>(out + (size_t)n * HDIM);
    const float4* e0 = reinterpret_cast<const float4*>(g_eo + r0);
    const float4* e1 = reinterpret_cast<const float4*>(g_eo + r1);
#pragma unroll
    for (int i = 0; i < 2; i++) {
        int idx = tid + i * 256;
        float4 v = o[idx], a = e0[idx], b = e1[idx];
        v.x += a.x + b.x; v.y += a.y + b.y;
        v.z += a.z + b.z; v.w += a.w + b.w;
        o[idx] = v;
    }
}

// ============================================================================
// Launch
// ============================================================================
extern "C" void kernel_launch(void* const* d_in, const int* in_sizes, int n_in,
                              void* d_out, int out_size) {
    const float* x = (const float*)d_in[0];       // [1024, 2048]
    const float* gw = (const float*)d_in[1];      // [2048, 8]
    const float* wgu = (const float*)d_in[2];     // [8, 2048, 2816]
    const float* wdn = (const float*)d_in[3];     // [8, 1408, 2048]
    const float* swgu = (const float*)d_in[4];    // [2048, 11264]
    const float* swdn = (const float*)d_in[5];    // [5632, 2048]
    const float* sgw = (const float*)d_in[6];     // [2048, 1]
    float* out = (float*)d_out;                   // [1024, 2048]

    cudaFuncSetAttribute(gateup_all, cudaFuncAttributeMaxDynamicSharedMemorySize, GU_SMEM);
    cudaFuncSetAttribute(down_all, cudaFuncAttributeMaxDynamicSharedMemorySize, DN_SMEM);

    zero_kernel<<<1, 32>>>();
    roundx_kernel<<<(NTOK * HDIM / 4) / 256, 256>>>(x);
    router_kernel<<<NTOK, 128>>>(x, gw, sgw);

    // All gate_up GEMMs (shared z=0 + experts z=1..8) in one launch.
    gateup_all<<<dim3(ISHA / 64, NTOK / 128, 1 + NEXP), 128, GU_SMEM>>>(swgu, wgu);

    // All down GEMMs in one launch: z=0 writes out, z>=1 writes g_eo (disjoint).
    down_all<<<dim3(HDIM / 128, NTOK / 128, 1 + NEXP), 128, DN_SMEM>>>(swdn, wdn, out);

    // Gather the two expert rows per token into out.
    combine_kernel<<<NTOK, 256>>>(out);
}

// round 11
// speedup vs baseline: 3.3606x; 1.3609x over previous
#include <cuda_runtime.h>
#include <cstdint>

// ============================================================================
// Problem constants
// ============================================================================
#define NTOK 1024
#define HDIM 2048
#define NEXP 8
#define IEXP 1408
#define ISHA 5632

// ============================================================================
// Scratch (allocation-free rule: __device__ globals)
// ============================================================================
__device__ float g_acts[(size_t)NTOK * ISHA];          // shared act (23MB)
__device__ float g_actr[(size_t)NEXP * NTOK * IEXP];   // routed act (46MB)
__device__ float g_eo[(size_t)NEXP * NTOK * HDIM];     // routed expert out (67MB)
__device__ float g_sg[NTOK];
__device__ int   g_cnt[NEXP];
__device__ int   g_tok[NEXP * NTOK];                   // expert -> token list
__device__ float g_wt[NEXP * NTOK];                    // expert -> routing weight / slot
__device__ int   g_slot[NTOK * 2];                     // token -> 2 global slots

// ============================================================================
// Helpers
// ============================================================================
__device__ __forceinline__ uint32_t smem_u32(const void* p) {
    uint32_t a;
    asm("{ .reg .u64 t; cvta.to.shared.u64 t, %1; cvt.u32.u64 %0, t; }" : "=r"(a) : "l"(p));
    return a;
}

// Pack two fp32 -> f16x2 (rne). Order consistent between A and B, so any
// lo/hi convention cancels in the MMA dot product.
__device__ __forceinline__ uint32_t pack_h2(float a, float b) {
    uint32_t r;
    asm("cvt.rn.f16x2.f32 %0, %1, %2;" : "=r"(r) : "f"(b), "f"(a));
    return r;
}

__device__ __forceinline__ void cp16(uint32_t dst, const float* src) {
    asm volatile("cp.async.cg.shared.global [%0], [%1], 16;" :: "r"(dst), "l"(src));
}
#define CP_COMMIT() asm volatile("cp.async.commit_group;" ::: "memory")
#define CP_WAIT(n)  asm volatile("cp.async.wait_group %0;" :: "n"(n) : "memory")

// m16n8k16 fp16 mma, fp32 accumulate
__device__ __forceinline__ void mma16(float* d, const uint32_t* a, const uint32_t* b) {
    asm volatile(
        "mma.sync.aligned.m16n8k16.row.col.f32.f16.f16.f32 "
        "{%0,%1,%2,%3}, {%4,%5,%6,%7}, {%8,%9}, {%0,%1,%2,%3};"
        : "+f"(d[0]), "+f"(d[1]), "+f"(d[2]), "+f"(d[3])
        : "r"(a[0]), "r"(a[1]), "r"(a[2]), "r"(a[3]), "r"(b[0]), "r"(b[1]));
}

// ============================================================================
// Small kernels
// ============================================================================
__global__ void zero_kernel() {
    if (threadIdx.x < NEXP) g_cnt[threadIdx.x] = 0;
}

// ============================================================================
// Router: softmax + top-2 -> per-expert token lists + token->slot map
// ============================================================================
__global__ void router_kernel(const float* __restrict__ x,
                              const float* __restrict__ gw,
                              const float* __restrict__ sgw) {
    const int n = blockIdx.x;
    const int tid = threadIdx.x;  // 128
    const float* xr = x + (size_t)n * HDIM;
    float acc[9];
#pragma unroll
    for (int j = 0; j < 9; j++) acc[j] = 0.f;
    for (int k = tid; k < HDIM; k += 128) {
        float xv = xr[k];
#pragma unroll
        for (int e = 0; e < NEXP; e++) acc[e] += xv * gw[k * NEXP + e];
        acc[8] += xv * sgw[k];
    }
    __shared__ float red[9][4];
#pragma unroll
    for (int j = 0; j < 9; j++) {
        float v = acc[j];
#pragma unroll
        for (int o = 16; o > 0; o >>= 1) v += __shfl_xor_sync(0xffffffffu, v, o);
        if ((tid & 31) == 0) red[j][tid >> 5] = v;
    }
    __syncthreads();
    if (tid == 0) {
        float lg[9];
#pragma unroll
        for (int j = 0; j < 9; j++) lg[j] = red[j][0] + red[j][1] + red[j][2] + red[j][3];
        float m = lg[0];
        for (int e = 1; e < NEXP; e++) m = fmaxf(m, lg[e]);
        float p[NEXP], s = 0.f;
        for (int e = 0; e < NEXP; e++) { p[e] = expf(lg[e] - m); s += p[e]; }
        for (int e = 0; e < NEXP; e++) p[e] /= s;
        int i1 = 0;
        for (int e = 1; e < NEXP; e++) if (p[e] > p[i1]) i1 = e;
        int i2 = (i1 == 0) ? 1 : 0;
        for (int e = 0; e < NEXP; e++) if (e != i1 && p[e] > p[i2]) i2 = e;
        int s1 = atomicAdd(&g_cnt[i1], 1);
        g_tok[i1 * NTOK + s1] = n;  g_wt[i1 * NTOK + s1] = p[i1];
        g_slot[n * 2] = i1 * NTOK + s1;
        int s2 = atomicAdd(&g_cnt[i2], 1);
        g_tok[i2 * NTOK + s2] = n;  g_wt[i2 * NTOK + s2] = p[i2];
        g_slot[n * 2 + 1] = i2 * NTOK + s2;
        g_sg[n] = 1.f / (1.f + expf(-lg[8]));
    }
}

// ============================================================================
// Merged gate_up GEMM + SiLU*mul  (z=0: shared, z=1..8: expert z-1)
//   fp16 m16n8k16 MMA, fp32 smem staging, cvt at fragment load.
//   CTA 128m x 64f, 128 threads, 4 warps each 64m x 64n (m-half x gate/up).
//   SMEM stage: As[128][40] (LDS.64-friendly), B 2 x [32][68] (P=68: 8tg+gid
//   bank-distinct). 2-stage cp.async. Epilogue: up warps exchange via smem.
// ============================================================================
#define GU_APAD 40
#define GU_BPAD 68
#define GU_ASZ (128 * GU_APAD)                  // 5120 floats
#define GU_BSZ (32 * GU_BPAD)                   // 2176 floats
#define GU_BUF (GU_ASZ + 2 * GU_BSZ)            // 9472 floats / stage
#define GU_SMEM (2 * GU_BUF * 4)                // 75776 bytes

__global__ __launch_bounds__(128, 3) void gateup_all(const float* __restrict__ X,
                                                     const float* __restrict__ Wsh,
                                                     const float* __restrict__ Wex) {
    const int z = blockIdx.z;
    const int m0 = blockIdx.y * 128;
    int F, cnt, ebase = 0;
    const float* W;
    float* actOut;
    if (z == 0) {
        F = ISHA; cnt = NTOK; W = Wsh; actOut = g_acts;
    } else {
        F = IEXP;
        if (blockIdx.x >= IEXP / 64) return;
        const int e = z - 1;
        cnt = g_cnt[e];
        if (m0 >= cnt) return;
        ebase = e * NTOK;
        W = Wex + (size_t)e * HDIM * 2 * IEXP;
        actOut = g_actr + (size_t)e * NTOK * IEXP;
    }
    const int f0 = blockIdx.x * 64;
    const int ldw = 2 * F;
    extern __shared__ float smem[];
    const int tid = threadIdx.x;
    const int wid = tid >> 5, lane = tid & 31;
    const int gid = lane >> 2, tg = lane & 3;
    const int wm = (wid & 1) * 64;       // m-half
    const int uphalf = wid >> 1;         // 0 = gate, 1 = up
    const uint32_t sb = smem_u32(smem);

    // ---- staging addressing ----
    const int aRow0 = tid >> 3, aQ = tid & 7;
    uint32_t aByte[8];                    // token row byte offsets into X
#pragma unroll
    for (int i = 0; i < 8; i++) {
        int row = aRow0 + 16 * i;
        int t;
        if (z > 0)
            t = g_tok[ebase + ((m0 + row < cnt) ? (m0 + row) : 0)];
        else
            t = m0 + row;
        aByte[i] = (uint32_t)t * (HDIM * 4);
    }
    const char* xbase = (const char*)X + aQ * 16;
    const uint32_t aDst0 = sb + (uint32_t)(aRow0 * GU_APAD + aQ * 4) * 4;
    const int bR0 = tid >> 4, bQ = tid & 15;
    const float* bBase = W + (size_t)bR0 * ldw + f0 + bQ * 4;
    const uint32_t bDst0 = sb + (uint32_t)(GU_ASZ + bR0 * GU_BPAD + bQ * 4) * 4;

    float acc[4][8][4];
#pragma unroll
    for (int mf = 0; mf < 4; mf++)
#pragma unroll
        for (int nf = 0; nf < 8; nf++)
#pragma unroll
            for (int r = 0; r < 4; r++) acc[mf][nf][r] = 0.f;

    // ---- prologue: stage 0 ----
#pragma unroll
    for (int i = 0; i < 8; i++)
        cp16(aDst0 + (uint32_t)(i * 16 * GU_APAD * 4),
             (const float*)(xbase + aByte[i]));
#pragma unroll
    for (int i = 0; i < 8; i++) {
        int half = i >> 2, rr = i & 3;
        cp16(bDst0 + (uint32_t)((half * GU_BSZ + rr * 8 * GU_BPAD) * 4),
             bBase + (size_t)(half ? F : 0) + (size_t)(rr * 8) * ldw);
    }
    CP_COMMIT();

    int buf = 0;
    const int kIters = HDIM / 32;  // 64
    for (int kt = 0; kt < kIters; kt++) {
        if (kt + 1 < kIters) {
            const uint32_t bufOff = (uint32_t)(((buf ^ 1) * GU_BUF) * 4);
            const int k0 = (kt + 1) * 32;
#pragma unroll
            for (int i = 0; i < 8; i++)
                cp16(aDst0 + bufOff + (uint32_t)(i * 16 * GU_APAD * 4),
                     (const float*)(xbase + aByte[i]) + k0);
#pragma unroll
            for (int i = 0; i < 8; i++) {
                int half = i >> 2, rr = i & 3;
                cp16(bDst0 + bufOff + (uint32_t)((half * GU_BSZ + rr * 8 * GU_BPAD) * 4),
                     bBase + (size_t)(half ? F : 0) + (size_t)(k0 + rr * 8) * ldw);
            }
            CP_COMMIT();
            CP_WAIT(1);
        } else {
            CP_WAIT(0);
        }
        __syncthreads();

        const float* As = smem + buf * GU_BUF;
        const float* Bs = As + GU_ASZ + uphalf * GU_BSZ;
        // 2 x k16 steps per 32-wide k-tile
#pragma unroll
        for (int ks = 0; ks < 2; ks++) {
            const int k0 = ks * 16;
            uint32_t a[4][4];
#pragma unroll
            for (int mf = 0; mf < 4; mf++) {
                int r = wm + mf * 16 + gid;
                float2 p0 = *(const float2*)(As + r * GU_APAD + k0 + 2 * tg);
                float2 p1 = *(const float2*)(As + (r + 8) * GU_APAD + k0 + 2 * tg);
                float2 p2 = *(const float2*)(As + r * GU_APAD + k0 + 2 * tg + 8);
                float2 p3 = *(const float2*)(As + (r + 8) * GU_APAD + k0 + 2 * tg + 8);
                a[mf][0] = pack_h2(p0.x, p0.y);
                a[mf][1] = pack_h2(p1.x, p1.y);
                a[mf][2] = pack_h2(p2.x, p2.y);
                a[mf][3] = pack_h2(p3.x, p3.y);
            }
#pragma unroll
            for (int nf = 0; nf < 8; nf++) {
                int n = nf * 8 + gid;
                uint32_t b[2];
                b[0] = pack_h2(Bs[(k0 + 2 * tg) * GU_BPAD + n],
                               Bs[(k0 + 2 * tg + 1) * GU_BPAD + n]);
                b[1] = pack_h2(Bs[(k0 + 2 * tg + 8) * GU_BPAD + n],
                               Bs[(k0 + 2 * tg + 9) * GU_BPAD + n]);
#pragma unroll
                for (int mf = 0; mf < 4; mf++) mma16(acc[mf][nf], a[mf], b);
            }
        }
        __syncthreads();
        buf ^= 1;
    }

    // ---- epilogue: exchange up through smem, gate warps combine ----
    if (uphalf) {
#pragma unroll
        for (int mf = 0; mf < 4; mf++)
#pragma unroll
            for (int h = 0; h < 2; h++) {
                int row = wm + mf * 16 + gid + h * 8;
#pragma unroll
                for (int nf = 0; nf < 8; nf++) {
                    int col = nf * 8 + 2 * tg;
                    smem[row * 72 + col]     = acc[mf][nf][2 * h];
                    smem[row * 72 + col + 1] = acc[mf][nf][2 * h + 1];
                }
            }
    }
    __syncthreads();
    if (!uphalf) {
#pragma unroll
        for (int mf = 0; mf < 4; mf++)
#pragma unroll
            for (int h = 0; h < 2; h++) {
                int row = wm + mf * 16 + gid + h * 8;
                float* orow = actOut + (size_t)(m0 + row) * F + f0;
#pragma unroll
                for (int nf = 0; nf < 8; nf++) {
                    int col = nf * 8 + 2 * tg;
                    float g0 = acc[mf][nf][2 * h];
                    float g1 = acc[mf][nf][2 * h + 1];
                    float u0 = smem[row * 72 + col];
                    float u1 = smem[row * 72 + col + 1];
                    float s0 = g0 / (1.0f + __expf(-g0));
                    float s1 = g1 / (1.0f + __expf(-g1));
                    orow[col]     = s0 * u0;
                    orow[col + 1] = s1 * u1;
                }
            }
    }
}

// ============================================================================
// Merged down GEMM  (z=0: shared -> out; z=1..8: expert -> g_eo)
//   fp16 m16n8k16. CTA 128m x 128n, 128 threads, 4 warps each 64m x 64n.
//   SMEM stage: As[128][40], Bs[32][132] (P=132: bank-distinct). 2-stage.
// ============================================================================
#define DN_APAD 40
#define DN_BPAD 132
#define DN_ASZ (128 * DN_APAD)                  // 5120 floats
#define DN_BSZ (32 * DN_BPAD)                   // 4224 floats
#define DN_BUF (DN_ASZ + DN_BSZ)                // 9344 floats / stage
#define DN_SMEM (2 * DN_BUF * 4)                // 74752 bytes

__global__ __launch_bounds__(128, 3) void down_all(const float* __restrict__ Wdsh,
                                                   const float* __restrict__ Wdex,
                                                   float* __restrict__ out) {
    const int z = blockIdx.z;
    const int m0 = blockIdx.y * 128;
    int Fk, cnt, ebase = 0;
    const float* Wd;
    const float* A;
    if (z == 0) {
        Fk = ISHA; cnt = NTOK; Wd = Wdsh; A = g_acts;
    } else {
        Fk = IEXP;
        const int e = z - 1;
        cnt = g_cnt[e];
        if (m0 >= cnt) return;
        ebase = e * NTOK;
        Wd = Wdex + (size_t)e * IEXP * HDIM;
        A = g_actr + (size_t)e * NTOK * IEXP;
    }
    const int n0 = blockIdx.x * 128;
    extern __shared__ float smem[];
    const int tid = threadIdx.x;
    const int wid = tid >> 5, lane = tid & 31;
    const int gid = lane >> 2, tg = lane & 3;
    const int wm = (wid & 1) * 64;
    const int wn = (wid >> 1) * 64;
    const int kIters = Fk / 32;
    const uint32_t sb = smem_u32(smem);

    const int aRow0 = tid >> 3, aQ = tid & 7;
    const float* aBase = A + (size_t)(m0 + aRow0) * Fk + aQ * 4;
    const size_t aStride = (size_t)16 * Fk;
    const uint32_t aDst0 = sb + (uint32_t)(aRow0 * DN_APAD + aQ * 4) * 4;
    const int bR0 = tid >> 5, bQ = tid & 31;
    const float* bBase = Wd + (size_t)bR0 * HDIM + n0 + bQ * 4;
    const uint32_t bDst0 = sb + (uint32_t)(DN_ASZ + bR0 * DN_BPAD + bQ * 4) * 4;

    float acc[4][8][4];
#pragma unroll
    for (int mf = 0; mf < 4; mf++)
#pragma unroll
        for (int nf = 0; nf < 8; nf++)
#pragma unroll
            for (int r = 0; r < 4; r++) acc[mf][nf][r] = 0.f;

#pragma unroll
    for (int i = 0; i < 8; i++)
        cp16(aDst0 + (uint32_t)(i * 16 * DN_APAD * 4), aBase + (size_t)i * aStride);
#pragma unroll
    for (int i = 0; i < 8; i++)
        cp16(bDst0 + (uint32_t)(i * 4 * DN_BPAD * 4), bBase + (size_t)(i * 4) * HDIM);
    CP_COMMIT();

    int buf = 0;
    for (int kt = 0; kt < kIters; kt++) {
        if (kt + 1 < kIters) {
            const uint32_t bufOff = (uint32_t)(((buf ^ 1) * DN_BUF) * 4);
            const int k0 = (kt + 1) * 32;
#pragma unroll
            for (int i = 0; i < 8; i++)
                cp16(aDst0 + bufOff + (uint32_t)(i * 16 * DN_APAD * 4),
                     aBase + (size_t)i * aStride + k0);
#pragma unroll
            for (int i = 0; i < 8; i++)
                cp16(bDst0 + bufOff + (uint32_t)(i * 4 * DN_BPAD * 4),
                     bBase + (size_t)(k0 + i * 4) * HDIM);
            CP_COMMIT();
            CP_WAIT(1);
        } else {
            CP_WAIT(0);
        }
        __syncthreads();

        const float* As = smem + buf * DN_BUF;
        const float* Bs = As + DN_ASZ;
#pragma unroll
        for (int ks = 0; ks < 2; ks++) {
            const int k0 = ks * 16;
            uint32_t a[4][4];
#pragma unroll
            for (int mf = 0; mf < 4; mf++) {
                int r = wm + mf * 16 + gid;
                float2 p0 = *(const float2*)(As + r * DN_APAD + k0 + 2 * tg);
                float2 p1 = *(const float2*)(As + (r + 8) * DN_APAD + k0 + 2 * tg);
                float2 p2 = *(const float2*)(As + r * DN_APAD + k0 + 2 * tg + 8);
                float2 p3 = *(const float2*)(As + (r + 8) * DN_APAD + k0 + 2 * tg + 8);
                a[mf][0] = pack_h2(p0.x, p0.y);
                a[mf][1] = pack_h2(p1.x, p1.y);
                a[mf][2] = pack_h2(p2.x, p2.y);
                a[mf][3] = pack_h2(p3.x, p3.y);
            }
#pragma unroll
            for (int nf = 0; nf < 8; nf++) {
                int n = wn + nf * 8 + gid;
                uint32_t b[2];
                b[0] = pack_h2(Bs[(k0 + 2 * tg) * DN_BPAD + n],
                               Bs[(k0 + 2 * tg + 1) * DN_BPAD + n]);
                b[1] = pack_h2(Bs[(k0 + 2 * tg + 8) * DN_BPAD + n],
                               Bs[(k0 + 2 * tg + 9) * DN_BPAD + n]);
#pragma unroll
                for (int mf = 0; mf < 4; mf++) mma16(acc[mf][nf], a[mf], b);
            }
        }
        __syncthreads();
        buf ^= 1;
    }

    // Epilogue
#pragma unroll
    for (int mf = 0; mf < 4; mf++) {
#pragma unroll
        for (int h = 0; h < 2; h++) {
            int slot = m0 + wm + mf * 16 + gid + h * 8;
            float wv;
            float* orow;
            if (z == 0) {
                wv = g_sg[slot];
                orow = out + (size_t)slot * HDIM;
            } else {
                if (slot >= cnt) continue;
                wv = g_wt[ebase + slot];
                orow = g_eo + (size_t)(ebase + slot) * HDIM;
            }
#pragma unroll
            for (int nf = 0; nf < 8; nf++) {
                int col = n0 + wn + nf * 8 + 2 * tg;
                orow[col]     = wv * acc[mf][nf][2 * h];
                orow[col + 1] = wv * acc[mf][nf][2 * h + 1];
            }
        }
    }
}

// ============================================================================
// Combine: out[token] += g_eo[slotA] + g_eo[slotB]   (weights pre-applied)
// ============================================================================
__global__ void combine_kernel(float* __restrict__ out) {
    const int n = blockIdx.x;
    const int tid = threadIdx.x;  // 256
    const size_t r0 = (size_t)g_slot[n * 2] * HDIM;
    const size_t r1 = (size_t)g_slot[n * 2 + 1] * HDIM;
    float4* o = reinterpret_cast<float4*>(out + (size_t)n * HDIM);
    const float4* e0 = reinterpret_cast<const float4*>(g_eo + r0);
    const float4* e1 = reinterpret_cast<const float4*>(g_eo + r1);
#pragma unroll
    for (int i = 0; i < 2; i++) {
        int idx = tid + i * 256;
        float4 v = o[idx], a = e0[idx], b = e1[idx];
        v.x += a.x + b.x; v.y += a.y + b.y;
        v.z += a.z + b.z; v.w += a.w + b.w;
        o[idx] = v;
    }
}

// ============================================================================
// Launch
// ============================================================================
extern "C" void kernel_launch(void* const* d_in, const int* in_sizes, int n_in,
                              void* d_out, int out_size) {
    const float* x = (const float*)d_in[0];       // [1024, 2048]
    const float* gw = (const float*)d_in[1];      // [2048, 8]
    const float* wgu = (const float*)d_in[2];     // [8, 2048, 2816]
    const float* wdn = (const float*)d_in[3];     // [8, 1408, 2048]
    const float* swgu = (const float*)d_in[4];    // [2048, 11264]
    const float* swdn = (const float*)d_in[5];    // [5632, 2048]
    const float* sgw = (const float*)d_in[6];     // [2048, 1]
    float* out = (float*)d_out;                   // [1024, 2048]

    cudaFuncSetAttribute(gateup_all, cudaFuncAttributeMaxDynamicSharedMemorySize, GU_SMEM);
    cudaFuncSetAttribute(down_all, cudaFuncAttributeMaxDynamicSharedMemorySize, DN_SMEM);

    zero_kernel<<<1, 32>>>();
    router_kernel<<<NTOK, 128>>>(x, gw, sgw);

    // All gate_up GEMMs (shared z=0 + experts z=1..8) in one launch.
    gateup_all<<<dim3(ISHA / 64, NTOK / 128, 1 + NEXP), 128, GU_SMEM>>>(x, swgu, wgu);

    // All down GEMMs in one launch: z=0 writes out, z>=1 writes g_eo (disjoint).
    down_all<<<dim3(HDIM / 128, NTOK / 128, 1 + NEXP), 128, DN_SMEM>>>(swdn, wdn, out);

    // Gather the two expert rows per token into out.
    combine_kernel<<<NTOK, 256>>>(out);
}